// round 5
// baseline (speedup 1.0000x reference)
#include <cuda_runtime.h>
#include <cstdint>

#define TLEN 1024
#define BSZ  128
#define DIN  64
#define HD   512
#define RCTA 64          // recurrence CTAs (64 x 32 gate-cols = 2048)
#define RTHR 128

// ---------------- device scratch (static, no allocations) ----------------
__device__ float g_xg[(size_t)TLEN * 64 * 128 * 32];   // 1 GB: [t][cg][thr][32] frag-layout
__device__ float g_h0[(size_t)TLEN * BSZ * HD];        // 256 MB: layer0 h trace [t][b][u]
__device__ float g_h1[2][BSZ * HD];                    // layer1 h double buffer [b][u]
__device__ float g_zero[BSZ * HD];                     // stays zero
__device__ unsigned g_bar_cnt;
__device__ volatile unsigned g_bar_gen;

// ---------------- helpers ----------------
__device__ __forceinline__ uint32_t tf32u(float x) {
    uint32_t u; asm("cvt.rna.tf32.f32 %0, %1;" : "=r"(u) : "f"(x)); return u;
}
__device__ __forceinline__ float tf32r(float x) { return __uint_as_float(tf32u(x)); }

__device__ __forceinline__ void mma8(float d[4], const uint32_t a[4], const uint32_t b[2]) {
    asm volatile("mma.sync.aligned.m16n8k8.row.col.f32.tf32.tf32.f32 "
        "{%0,%1,%2,%3}, {%4,%5,%6,%7}, {%8,%9}, {%0,%1,%2,%3};"
        : "+f"(d[0]), "+f"(d[1]), "+f"(d[2]), "+f"(d[3])
        : "r"(a[0]), "r"(a[1]), "r"(a[2]), "r"(a[3]), "r"(b[0]), "r"(b[1]));
}

__device__ __forceinline__ float sigm(float x) { return 1.0f / (1.0f + __expf(-x)); }

// Replay-safe grid barrier (monotonic generation, counter self-resets).
__device__ __forceinline__ void grid_sync() {
    __syncthreads();
    if (threadIdx.x == 0) {
        __threadfence();
        unsigned cur = g_bar_gen;
        unsigned arr = atomicAdd(&g_bar_cnt, 1u);
        if (arr == RCTA - 1) {
            atomicExch(&g_bar_cnt, 0u);
            __threadfence();
            atomicAdd((unsigned int*)&g_bar_gen, 1u);
        } else {
            while (*(volatile unsigned*)&g_bar_gen == cur) { __nanosleep(32); }
        }
        __threadfence();
    }
    __syncthreads();
}

// =====================================================================
// Transform pass: xg[t, col, b] = sum_k A[t, b, k] * Wih[col, k] + bih + bhh
// Written in the recurrence's per-thread fragment layout.
// Grid (32 colpairs, 128 tgroups), 256 thr. Each block: 64 cols, 8 t's.
// =====================================================================
__global__ void __launch_bounds__(256, 1)
xform(const float* __restrict__ Aptr, int srcmode, size_t t_stride, int row_stride, int Kin,
      const float* __restrict__ Wih, const float* __restrict__ bih,
      const float* __restrict__ bhh)
{
    extern __shared__ float sm[];
    float* Ws = sm;                 // [Kin][72 pad], 64 cols
    float* bs = sm + Kin * 72;      // 64 biases

    const float* A = srcmode ? g_h0 : Aptr;
    const int tid = threadIdx.x, l = tid & 31, wg = tid >> 5;
    const int w4 = wg & 3, cgl = wg >> 2;
    const int cgp = blockIdx.x;
    const int g4 = l >> 2, tq = l & 3;

    for (int i = tid; i < Kin * 64; i += 256) {
        int k = i >> 6, c = i & 63;
        int cl2 = c >> 5, gate = (c >> 3) & 3, u = c & 7;
        int row = gate * HD + (cgp * 2 + cl2) * 8 + u;
        Ws[k * 72 + c] = tf32r(Wih[(size_t)row * Kin + k]);
    }
    if (tid < 64) {
        int cl2 = tid >> 5, gate = (tid >> 3) & 3, u = tid & 7;
        int row = gate * HD + (cgp * 2 + cl2) * 8 + u;
        bs[tid] = bih[row] + bhh[row];
    }
    __syncthreads();

    const int r0 = w4 * 32 + g4;
    const int cg = cgp * 2 + cgl;
    const int nch = Kin >> 3;

    for (int tt = 0; tt < 8; ++tt) {
        const int t = blockIdx.y * 8 + tt;
        const float* ab  = A + (size_t)t * t_stride;
        const float* a00 = ab + (size_t)r0 * row_stride + tq;
        const float* a01 = a00 + (size_t)8  * row_stride;
        const float* a10 = a00 + (size_t)16 * row_stride;
        const float* a11 = a00 + (size_t)24 * row_stride;

        float D[2][4][4];
        #pragma unroll
        for (int m = 0; m < 2; ++m)
            #pragma unroll
            for (int g = 0; g < 4; ++g) {
                float b0 = bs[cgl * 32 + g * 8 + 2 * tq];
                float b1 = bs[cgl * 32 + g * 8 + 2 * tq + 1];
                D[m][g][0] = b0; D[m][g][1] = b1; D[m][g][2] = b0; D[m][g][3] = b1;
            }

        #pragma unroll 4
        for (int kc = 0; kc < nch; ++kc) {
            const int ko = kc * 8;
            uint32_t a0[4] = { tf32u(a00[ko]), tf32u(a01[ko]),
                               tf32u(a00[ko + 4]), tf32u(a01[ko + 4]) };
            uint32_t a1[4] = { tf32u(a10[ko]), tf32u(a11[ko]),
                               tf32u(a10[ko + 4]), tf32u(a11[ko + 4]) };
            const float* wb  = Ws + (size_t)(ko + tq) * 72 + cgl * 32 + g4;
            const float* wb4 = wb + 4 * 72;
            #pragma unroll
            for (int g = 0; g < 4; ++g) {
                uint32_t b[2] = { __float_as_uint(wb[g * 8]), __float_as_uint(wb4[g * 8]) };
                mma8(D[0][g], a0, b);
                mma8(D[1][g], a1, b);
            }
        }

        float4* dst = (float4*)(g_xg + ((((size_t)t * 64 + cg) * 128) + (w4 * 32 + l)) * 32);
        #pragma unroll
        for (int m = 0; m < 2; ++m)
            #pragma unroll
            for (int g = 0; g < 4; ++g)
                dst[m * 4 + g] = make_float4(D[m][g][0], D[m][g][1], D[m][g][2], D[m][g][3]);
    }
}

// =====================================================================
// Recurrence: 64 persistent CTAs, 128 thr; CTA cg owns 32 gate-cols
// (col = gate*8 + unit, units cg*8..cg*8+7). W_hh slice in smem.
// Per step: D = xg-frag; 64 k-chunks mma.sync (A = h from L2); gates.
// =====================================================================
__global__ void __launch_bounds__(RTHR, 1)
rec(int layer, const float* __restrict__ Whh,
    const float* __restrict__ fc1w, const float* __restrict__ fc1b,
    const float* __restrict__ fc2w, const float* __restrict__ fc2b,
    float* __restrict__ out, int do_fc)
{
    extern __shared__ float sm[];
    float* Ws = sm;                  // [512][40 pad], 32 cols

    const int tid = threadIdx.x, l = tid & 31, w = tid >> 5;
    const int g4 = l >> 2, tq = l & 3;
    const int cg = blockIdx.x;

    for (int i = tid; i < HD * 32; i += RTHR) {
        int k = i >> 5, c = i & 31;
        int gate = c >> 3, u = c & 7;
        int row = gate * HD + cg * 8 + u;
        Ws[k * 40 + c] = tf32r(Whh[(size_t)row * HD + k]);
    }
    __syncthreads();

    float cst[8];
    #pragma unroll
    for (int s = 0; s < 8; ++s) cst[s] = 0.0f;
    const int r0 = w * 32 + g4;

    for (int t = 0; t < TLEN; ++t) {
        const float* hp = layer ? (t ? g_h1[(t - 1) & 1] : g_zero)
                                : (t ? g_h0 + (size_t)(t - 1) * (BSZ * HD) : g_zero);
        const float* a00 = hp + (size_t)r0 * HD + tq;
        const float* a01 = a00 + 8 * HD;
        const float* a10 = a00 + 16 * HD;
        const float* a11 = a00 + 24 * HD;

        float D[2][4][4];
        const float4* xp = (const float4*)(g_xg + (((size_t)t * 64 + cg) * 128 + tid) * 32);
        #pragma unroll
        for (int m = 0; m < 2; ++m)
            #pragma unroll
            for (int g = 0; g < 4; ++g) {
                float4 v = xp[m * 4 + g];
                D[m][g][0] = v.x; D[m][g][1] = v.y; D[m][g][2] = v.z; D[m][g][3] = v.w;
            }

        #pragma unroll 4
        for (int kc = 0; kc < 64; ++kc) {
            const int ko = kc * 8;
            // h values were tf32-rounded when written — no cvt needed here
            uint32_t a0[4] = { __float_as_uint(a00[ko]), __float_as_uint(a01[ko]),
                               __float_as_uint(a00[ko + 4]), __float_as_uint(a01[ko + 4]) };
            uint32_t a1[4] = { __float_as_uint(a10[ko]), __float_as_uint(a11[ko]),
                               __float_as_uint(a10[ko + 4]), __float_as_uint(a11[ko + 4]) };
            const float* wb  = Ws + (size_t)(ko + tq) * 40 + g4;
            const float* wb4 = wb + 4 * 40;
            #pragma unroll
            for (int g = 0; g < 4; ++g) {
                uint32_t b[2] = { __float_as_uint(wb[g * 8]), __float_as_uint(wb4[g * 8]) };
                mma8(D[0][g], a0, b);
                mma8(D[1][g], a1, b);
            }
        }

        float* ho = layer ? g_h1[t & 1] : g_h0 + (size_t)t * (BSZ * HD);
        #pragma unroll
        for (int m = 0; m < 2; ++m)
            #pragma unroll
            for (int rr = 0; rr < 2; ++rr) {
                float h2[2];
                #pragma unroll
                for (int j = 0; j < 2; ++j) {
                    int q = rr * 2 + j;
                    float gi = sigm(D[m][0][q]);
                    float gf = sigm(D[m][1][q]);
                    float gv = tanhf(D[m][2][q]);
                    float go = sigm(D[m][3][q]);
                    int s = m * 4 + rr * 2 + j;
                    cst[s] = gf * cst[s] + gi * gv;
                    h2[j] = tf32r(go * tanhf(cst[s]));
                }
                int row = r0 + m * 16 + rr * 8;
                *(float2*)(ho + (size_t)row * HD + cg * 8 + 2 * tq) = make_float2(h2[0], h2[1]);
            }
        grid_sync();
    }

    // ---------------- FC head (layer 1 only, CTA 0) ----------------
    if (do_fc && cg == 0) {
        for (int i = tid; i < HD * 32; i += RTHR) {
            int u = i >> 5, j = i & 31;
            Ws[i] = fc1w[j * HD + u];
        }
        __syncthreads();
        const float* hf = g_h1[(TLEN - 1) & 1];
        float s[32];
        #pragma unroll
        for (int j = 0; j < 32; ++j) s[j] = 0.0f;
        for (int u = 0; u < HD; ++u) {
            float v = hf[(size_t)tid * HD + u];
            const float4* ww = (const float4*)(Ws + u * 32);
            #pragma unroll
            for (int j4 = 0; j4 < 8; ++j4) {
                float4 wv = ww[j4];
                s[4 * j4 + 0] += v * wv.x;
                s[4 * j4 + 1] += v * wv.y;
                s[4 * j4 + 2] += v * wv.z;
                s[4 * j4 + 3] += v * wv.w;
            }
        }
        float y = fc2b[0];
        #pragma unroll
        for (int j = 0; j < 32; ++j) y += fc2w[j] * (s[j] + fc1b[j]);
        out[tid] = y;
    }
}

// =====================================================================
extern "C" void kernel_launch(void* const* d_in, const int* in_sizes, int n_in,
                              void* d_out, int out_size)
{
    (void)in_sizes; (void)n_in; (void)out_size;
    const float* x    = (const float*)d_in[0];
    const float* Wih0 = (const float*)d_in[1];
    const float* Whh0 = (const float*)d_in[2];
    const float* bih0 = (const float*)d_in[3];
    const float* bhh0 = (const float*)d_in[4];
    const float* Wih1 = (const float*)d_in[5];
    const float* Whh1 = (const float*)d_in[6];
    const float* bih1 = (const float*)d_in[7];
    const float* bhh1 = (const float*)d_in[8];
    const float* fc1w = (const float*)d_in[9];
    const float* fc1b = (const float*)d_in[10];
    const float* fc2w = (const float*)d_in[11];
    const float* fc2b = (const float*)d_in[12];
    float* out = (float*)d_out;

    const size_t sm_x0 = (size_t)(DIN * 72 + 64) * 4;
    const size_t sm_x1 = (size_t)(HD * 72 + 64) * 4;
    const size_t sm_r  = (size_t)(HD * 40) * 4;
    cudaFuncSetAttribute(xform, cudaFuncAttributeMaxDynamicSharedMemorySize, (int)sm_x1);
    cudaFuncSetAttribute(rec,   cudaFuncAttributeMaxDynamicSharedMemorySize, (int)sm_r);

    dim3 gx(32, TLEN / 8);
    // layer 0: A = x [b][t][64] -> t_stride=64, row_stride=TLEN*DIN
    xform<<<gx, 256, sm_x0>>>(x, 0, (size_t)DIN, TLEN * DIN, DIN, Wih0, bih0, bhh0);
    rec<<<RCTA, RTHR, sm_r>>>(0, Whh0, fc1w, fc1b, fc2w, fc2b, out, 0);
    // layer 1: A = g_h0 [t][b][512] -> t_stride=BSZ*HD, row_stride=HD
    xform<<<gx, 256, sm_x1>>>(nullptr, 1, (size_t)(BSZ * HD), HD, HD, Wih1, bih1, bhh1);
    rec<<<RCTA, RTHR, sm_r>>>(1, Whh1, fc1w, fc1b, fc2w, fc2b, out, 1);
}

// round 6
// speedup vs baseline: 1.5353x; 1.5353x over previous
#include <cuda_runtime.h>
#include <cstdint>

#define TLEN 1024
#define BSZ  128
#define DIN  64
#define HD   512
#define L0N  32
#define L1N  64
#define NCTA (L0N + L1N)
#define NTHR 256

#define WST0 68     // W smem row stride (floats), L0 (64 cols)
#define WST1 36     // W smem row stride (floats), L1 (32 cols)
#define TST  68     // A-tile smem row stride (floats)

// dynamic smem byte offsets (rec kernel)
#define OFF_BIAS 147456                  // after W region (max 1024*36*4)
#define OFF_T0   147712
#define OFF_T1   (147712 + 34816)
#define SMEM_REC (OFF_T1 + 34816)        // 217,344 B

// ---------------- device scratch (static, no allocations) ----------------
__device__ float g_xg[(size_t)TLEN * L0N * NTHR * 32];  // 1 GB: L0 frag init [t][cg][tid][32]
__device__ float g_h0[2][BSZ * HD];
__device__ float g_h1[2][BSZ * HD];
__device__ float g_zero[BSZ * HD];       // stays zero
__device__ unsigned g_bar_cnt;
__device__ volatile unsigned g_bar_gen;

// ---------------- helpers ----------------
__device__ __forceinline__ uint32_t tf32u(float x) {
    uint32_t u; asm("cvt.rna.tf32.f32 %0, %1;" : "=r"(u) : "f"(x)); return u;
}
__device__ __forceinline__ float tf32r(float x) { return __uint_as_float(tf32u(x)); }

__device__ __forceinline__ void mma8(float d[4], const uint32_t a[4], const uint32_t b[2]) {
    asm volatile("mma.sync.aligned.m16n8k8.row.col.f32.tf32.tf32.f32 "
        "{%0,%1,%2,%3}, {%4,%5,%6,%7}, {%8,%9}, {%0,%1,%2,%3};"
        : "+f"(d[0]), "+f"(d[1]), "+f"(d[2]), "+f"(d[3])
        : "r"(a[0]), "r"(a[1]), "r"(a[2]), "r"(a[3]), "r"(b[0]), "r"(b[1]));
}

__device__ __forceinline__ float sigm(float x)  { return 1.0f / (1.0f + __expf(-x)); }
__device__ __forceinline__ float tanhp(float x) { return 2.0f / (1.0f + __expf(-2.0f * x)) - 1.0f; }

// Replay-safe grid barrier (monotonic generation, counter self-resets).
__device__ __forceinline__ void grid_sync() {
    __syncthreads();
    if (threadIdx.x == 0) {
        __threadfence();
        unsigned cur = g_bar_gen;
        unsigned arr = atomicAdd(&g_bar_cnt, 1u);
        if (arr == NCTA - 1) {
            atomicExch(&g_bar_cnt, 0u);
            __threadfence();
            atomicAdd((unsigned int*)&g_bar_gen, 1u);
        } else {
            while (*(volatile unsigned*)&g_bar_gen == cur) { __nanosleep(32); }
        }
        __threadfence();
    }
    __syncthreads();
}

// =====================================================================
// xform0: g_xg = bias + x @ Wih0^T, stored in rec-L0 per-thread frag layout.
// Grid (32 cg, TLEN/8); block computes 64 cols x 128 rows for 8 t's. K=64.
// =====================================================================
__global__ void __launch_bounds__(NTHR, 1)
xform0(const float* __restrict__ x, const float* __restrict__ Wih,
       const float* __restrict__ bih, const float* __restrict__ bhh)
{
    extern __shared__ float sm[];
    float* Ws = sm;                 // [64][WST0]
    float* bs = sm + 64 * WST0;     // 64 biases

    const int tid = threadIdx.x, l = tid & 31, w = tid >> 5;
    const int g4 = l >> 2, tq = l & 3, wrow = w * 16;
    const int cg = blockIdx.x;

    for (int i = tid; i < 64 * 64; i += NTHR) {
        int k = i >> 6, c = i & 63;
        int gate = c >> 4, uh = (c >> 3) & 1, s = c & 7;
        int grow = gate * HD + cg * 16 + uh * 8 + s;
        Ws[k * WST0 + c] = tf32r(Wih[(size_t)grow * DIN + k]);
    }
    if (tid < 64) {
        int gate = tid >> 4, uh = (tid >> 3) & 1, s = tid & 7;
        int grow = gate * HD + cg * 16 + uh * 8 + s;
        bs[tid] = bih[grow] + bhh[grow];
    }
    __syncthreads();

    const int r = wrow + g4;
    for (int tt = 0; tt < 8; ++tt) {
        const int t = blockIdx.y * 8 + tt;
        const float* a0p = x + (size_t)r * (TLEN * DIN) + (size_t)t * DIN;
        const float* a1p = a0p + (size_t)8 * (TLEN * DIN);

        float D[8][4];
        #pragma unroll
        for (int j = 0; j < 8; ++j) {
            float b0 = bs[j * 8 + 2 * tq], b1 = bs[j * 8 + 2 * tq + 1];
            D[j][0] = b0; D[j][1] = b1; D[j][2] = b0; D[j][3] = b1;
        }
        #pragma unroll
        for (int kk = 0; kk < 8; ++kk) {
            int ko = kk * 8;
            uint32_t a[4] = { tf32u(a0p[ko + tq]), tf32u(a1p[ko + tq]),
                              tf32u(a0p[ko + tq + 4]), tf32u(a1p[ko + tq + 4]) };
            const float* wp  = Ws + (ko + tq) * WST0 + g4;
            const float* wp4 = wp + 4 * WST0;
            #pragma unroll
            for (int j = 0; j < 8; ++j) {
                uint32_t b[2] = { __float_as_uint(wp[j * 8]), __float_as_uint(wp4[j * 8]) };
                mma8(D[j], a, b);
            }
        }
        float4* dst = (float4*)(g_xg + (((size_t)t * L0N + cg) * NTHR + tid) * 32);
        #pragma unroll
        for (int j = 0; j < 8; ++j)
            dst[j] = make_float4(D[j][0], D[j][1], D[j][2], D[j][3]);
    }
}

// =====================================================================
// rec_all: persistent, 96 CTAs. CTA<32: layer0 (64 cols, K=512).
// CTA>=32: layer1 (32 cols, K=1024 = [h0(t); h1(t-1)]), one epoch behind.
// Per epoch: double-buffered smem A-tiles (128x64), mma.sync tf32, gates.
// =====================================================================
__global__ void __launch_bounds__(NTHR, 1)
rec_all(const float* __restrict__ Whh0,
        const float* __restrict__ Wih1, const float* __restrict__ Whh1,
        const float* __restrict__ bih1, const float* __restrict__ bhh1,
        const float* __restrict__ fc1w, const float* __restrict__ fc1b,
        const float* __restrict__ fc2w, const float* __restrict__ fc2b,
        float* __restrict__ out)
{
    extern __shared__ float sm[];
    float* Ws = sm;
    float* bs = sm + OFF_BIAS / 4;
    float* tileA[2] = { sm + OFF_T0 / 4, sm + OFF_T1 / 4 };

    const int tid = threadIdx.x, l = tid & 31, w = tid >> 5;
    const int g4 = l >> 2, tq = l & 3, wrow = w * 16;
    const int cta = blockIdx.x;
    const bool is0 = (cta < L0N);
    const int trow = tid >> 4, tc4 = tid & 15;   // tile loader mapping

    // ---- stage weights (constant across time) ----
    if (is0) {
        const int cg = cta;
        for (int i = tid; i < HD * 64; i += NTHR) {
            int k = i >> 6, c = i & 63;
            int gate = c >> 4, uh = (c >> 3) & 1, s = c & 7;
            int grow = gate * HD + cg * 16 + uh * 8 + s;
            Ws[k * WST0 + c] = tf32r(Whh0[(size_t)grow * HD + k]);
        }
    } else {
        const int lc = cta - L0N;
        for (int i = tid; i < 2 * HD * 32; i += NTHR) {
            int k = i >> 5, c = i & 31;
            int gate = c >> 3, s = c & 7;
            int grow = gate * HD + lc * 8 + s;
            float v = (k < HD) ? Wih1[(size_t)grow * HD + k]
                               : Whh1[(size_t)grow * HD + (k - HD)];
            Ws[k * WST1 + c] = tf32r(v);
        }
        if (tid < 32) {
            int gate = tid >> 3, s = tid & 7;
            int grow = gate * HD + lc * 8 + s;
            bs[tid] = bih1[grow] + bhh1[grow];
        }
    }
    __syncthreads();

    float cst[8];
    #pragma unroll
    for (int s = 0; s < 8; ++s) cst[s] = 0.0f;

    for (int e = 0; e <= TLEN; ++e) {
        if (is0 && e < TLEN) {
            const int cg = cta;
            // prefetch xg frags (independent of barrier-protected h)
            const float4* xp = (const float4*)(g_xg + (((size_t)e * L0N + cg) * NTHR + tid) * 32);
            float4 xv[8];
            #pragma unroll
            for (int j = 0; j < 8; ++j) xv[j] = xp[j];

            const float* hsrc = e ? g_h0[(e - 1) & 1] : g_zero;
            float4 v[8];
            #pragma unroll
            for (int j = 0; j < 8; ++j)
                v[j] = *(const float4*)(hsrc + (size_t)(trow + 16 * j) * HD + tc4 * 4);
            #pragma unroll
            for (int j = 0; j < 8; ++j)
                *(float4*)(tileA[0] + (trow + 16 * j) * TST + tc4 * 4) = v[j];

            float D[8][4];
            #pragma unroll
            for (int j = 0; j < 8; ++j) {
                D[j][0] = xv[j].x; D[j][1] = xv[j].y; D[j][2] = xv[j].z; D[j][3] = xv[j].w;
            }
            __syncthreads();

            for (int tt = 0; tt < 8; ++tt) {
                const float* tb = tileA[tt & 1];
                if (tt < 7) {
                    #pragma unroll
                    for (int j = 0; j < 8; ++j)
                        v[j] = *(const float4*)(hsrc + (size_t)(trow + 16 * j) * HD
                                                + (tt + 1) * 64 + tc4 * 4);
                }
                #pragma unroll
                for (int kk = 0; kk < 8; ++kk) {
                    const float* ap = tb + (wrow + g4) * TST + kk * 8 + tq;
                    uint32_t a[4] = { __float_as_uint(ap[0]),
                                      __float_as_uint(ap[8 * TST]),
                                      __float_as_uint(ap[4]),
                                      __float_as_uint(ap[8 * TST + 4]) };
                    const float* wp  = Ws + ((tt * 8 + kk) * 8 + tq) * WST0 + g4;
                    const float* wp4 = wp + 4 * WST0;
                    #pragma unroll
                    for (int j = 0; j < 8; ++j) {
                        uint32_t b[2] = { __float_as_uint(wp[j * 8]),
                                          __float_as_uint(wp4[j * 8]) };
                        mma8(D[j], a, b);
                    }
                }
                if (tt < 7) {
                    float* nb = tileA[(tt + 1) & 1];
                    #pragma unroll
                    for (int j = 0; j < 8; ++j)
                        *(float4*)(nb + (trow + 16 * j) * TST + tc4 * 4) = v[j];
                }
                __syncthreads();
            }

            // epilogue: gates -> cell -> h
            float* hb = g_h0[e & 1];
            #pragma unroll
            for (int uh = 0; uh < 2; ++uh)
                #pragma unroll
                for (int m = 0; m < 2; ++m) {
                    float2 hv;
                    #pragma unroll
                    for (int up = 0; up < 2; ++up) {
                        int q = 2 * m + up;
                        float gi = sigm(D[0 + uh][q]);
                        float gf = sigm(D[2 + uh][q]);
                        float gg = tanhp(D[4 + uh][q]);
                        float go = sigm(D[6 + uh][q]);
                        int s = uh * 4 + m * 2 + up;
                        cst[s] = gf * cst[s] + gi * gg;
                        (&hv.x)[up] = tf32r(go * tanhp(cst[s]));
                    }
                    int row = wrow + g4 + m * 8;
                    *(float2*)(hb + (size_t)row * HD + cta * 16 + uh * 8 + 2 * tq) = hv;
                }
        } else if (!is0 && e >= 1) {
            const int lc = cta - L0N;
            const int t  = e - 1;
            const float* src0 = g_h0[(e - 1) & 1];                 // h0[t]
            const float* src1 = t ? g_h1[e & 1] : g_zero;          // h1[t-1]

            float4 v[8];
            #pragma unroll
            for (int j = 0; j < 8; ++j)
                v[j] = *(const float4*)(src0 + (size_t)(trow + 16 * j) * HD + tc4 * 4);
            #pragma unroll
            for (int j = 0; j < 8; ++j)
                *(float4*)(tileA[0] + (trow + 16 * j) * TST + tc4 * 4) = v[j];

            float D[4][4];
            #pragma unroll
            for (int g = 0; g < 4; ++g) {
                float b0 = bs[g * 8 + 2 * tq], b1 = bs[g * 8 + 2 * tq + 1];
                D[g][0] = b0; D[g][1] = b1; D[g][2] = b0; D[g][3] = b1;
            }
            __syncthreads();

            for (int tt = 0; tt < 16; ++tt) {
                const float* tb = tileA[tt & 1];
                if (tt < 15) {
                    const float* nsrc = (tt + 1 < 8) ? src0 : src1;
                    const int cb = (tt + 1) & 7;
                    #pragma unroll
                    for (int j = 0; j < 8; ++j)
                        v[j] = *(const float4*)(nsrc + (size_t)(trow + 16 * j) * HD
                                                + cb * 64 + tc4 * 4);
                }
                #pragma unroll
                for (int kk = 0; kk < 8; ++kk) {
                    const float* ap = tb + (wrow + g4) * TST + kk * 8 + tq;
                    uint32_t a[4] = { __float_as_uint(ap[0]),
                                      __float_as_uint(ap[8 * TST]),
                                      __float_as_uint(ap[4]),
                                      __float_as_uint(ap[8 * TST + 4]) };
                    const float* wp  = Ws + ((tt * 8 + kk) * 8 + tq) * WST1 + g4;
                    const float* wp4 = wp + 4 * WST1;
                    #pragma unroll
                    for (int g = 0; g < 4; ++g) {
                        uint32_t b[2] = { __float_as_uint(wp[g * 8]),
                                          __float_as_uint(wp4[g * 8]) };
                        mma8(D[g], a, b);
                    }
                }
                if (tt < 15) {
                    float* nb = tileA[(tt + 1) & 1];
                    #pragma unroll
                    for (int j = 0; j < 8; ++j)
                        *(float4*)(nb + (trow + 16 * j) * TST + tc4 * 4) = v[j];
                }
                __syncthreads();
            }

            float* hb = g_h1[t & 1];
            #pragma unroll
            for (int m = 0; m < 2; ++m) {
                float2 hv;
                #pragma unroll
                for (int up = 0; up < 2; ++up) {
                    int q = 2 * m + up;
                    float gi = sigm(D[0][q]);
                    float gf = sigm(D[1][q]);
                    float gg = tanhp(D[2][q]);
                    float go = sigm(D[3][q]);
                    int s = m * 2 + up;
                    cst[s] = gf * cst[s] + gi * gg;
                    (&hv.x)[up] = tf32r(go * tanhp(cst[s]));
                }
                int row = wrow + g4 + m * 8;
                *(float2*)(hb + (size_t)row * HD + lc * 8 + 2 * tq) = hv;
            }
        }
        grid_sync();
    }

    // ---------------- FC head on CTA 0 ----------------
    if (cta == 0) {
        for (int i = tid; i < HD * 32; i += NTHR) {
            int u = i >> 5, j = i & 31;
            Ws[i] = fc1w[j * HD + u];
        }
        __syncthreads();
        if (tid < BSZ) {
            const float* hf = g_h1[(TLEN - 1) & 1];
            float s[32];
            #pragma unroll
            for (int j = 0; j < 32; ++j) s[j] = 0.0f;
            for (int u = 0; u < HD; ++u) {
                float vv = hf[(size_t)tid * HD + u];
                const float4* ww = (const float4*)(Ws + u * 32);
                #pragma unroll
                for (int j4 = 0; j4 < 8; ++j4) {
                    float4 wv = ww[j4];
                    s[4 * j4 + 0] += vv * wv.x;
                    s[4 * j4 + 1] += vv * wv.y;
                    s[4 * j4 + 2] += vv * wv.z;
                    s[4 * j4 + 3] += vv * wv.w;
                }
            }
            float y = fc2b[0];
            #pragma unroll
            for (int j = 0; j < 32; ++j) y += fc2w[j] * (s[j] + fc1b[j]);
            out[tid] = y;
        }
    }
}

// =====================================================================
extern "C" void kernel_launch(void* const* d_in, const int* in_sizes, int n_in,
                              void* d_out, int out_size)
{
    (void)in_sizes; (void)n_in; (void)out_size;
    const float* x    = (const float*)d_in[0];
    const float* Wih0 = (const float*)d_in[1];
    const float* Whh0 = (const float*)d_in[2];
    const float* bih0 = (const float*)d_in[3];
    const float* bhh0 = (const float*)d_in[4];
    const float* Wih1 = (const float*)d_in[5];
    const float* Whh1 = (const float*)d_in[6];
    const float* bih1 = (const float*)d_in[7];
    const float* bhh1 = (const float*)d_in[8];
    const float* fc1w = (const float*)d_in[9];
    const float* fc1b = (const float*)d_in[10];
    const float* fc2w = (const float*)d_in[11];
    const float* fc2b = (const float*)d_in[12];
    float* out = (float*)d_out;

    const int sm_x = 64 * WST0 * 4 + 256;
    cudaFuncSetAttribute(xform0,  cudaFuncAttributeMaxDynamicSharedMemorySize, sm_x);
    cudaFuncSetAttribute(rec_all, cudaFuncAttributeMaxDynamicSharedMemorySize, SMEM_REC);

    xform0<<<dim3(L0N, TLEN / 8), NTHR, sm_x>>>(x, Wih0, bih0, bhh0);
    rec_all<<<NCTA, NTHR, SMEM_REC>>>(Whh0, Wih1, Whh1, bih1, bhh1,
                                      fc1w, fc1b, fc2w, fc2b, out);
}

// round 7
// speedup vs baseline: 3.2758x; 2.1337x over previous
#include <cuda_runtime.h>
#include <cuda_bf16.h>
#include <cstdint>

#define TLEN 1024
#define BSZ  128
#define DIN  64
#define HD   512
#define L0CTA 32
#define L1CTA 64
#define NCTA  96
#define NTHR  256

// fragment index: uint4 element for (16-row block R, k-chunk C, lane l); NC = 32
#define FIDX(R, C, l) ((((R) * 32 + (C)) * 32) + (l))

// ---------------- device scratch (static, no allocations) ----------------
__device__ float g_xg[268435456];          // 1 GB: L0 D-init frags [t][cta][w][mf*4+nf][l][4]
__device__ uint4 g_h0f[2][8192];           // h0 bf16 A-fragment layout, double buffered
__device__ uint4 g_h1f[2][8192];           // h1
__device__ uint4 g_zf[8192];               // stays zero
__device__ unsigned g_bar_cnt;
__device__ volatile unsigned g_bar_gen;

// ---------------- helpers ----------------
__device__ __forceinline__ uint32_t tf32u(float x) {
    uint32_t u; asm("cvt.rna.tf32.f32 %0, %1;" : "=r"(u) : "f"(x)); return u;
}
__device__ __forceinline__ float tf32r(float x) { return __uint_as_float(tf32u(x)); }

__device__ __forceinline__ void mma8(float d[4], const uint32_t a[4], uint32_t b0, uint32_t b1) {
    asm volatile("mma.sync.aligned.m16n8k8.row.col.f32.tf32.tf32.f32 "
        "{%0,%1,%2,%3}, {%4,%5,%6,%7}, {%8,%9}, {%0,%1,%2,%3};"
        : "+f"(d[0]), "+f"(d[1]), "+f"(d[2]), "+f"(d[3])
        : "r"(a[0]), "r"(a[1]), "r"(a[2]), "r"(a[3]), "r"(b0), "r"(b1));
}
__device__ __forceinline__ void mma16(float d[4], const uint32_t* a, uint32_t b0, uint32_t b1) {
    asm volatile("mma.sync.aligned.m16n8k16.row.col.f32.bf16.bf16.f32 "
        "{%0,%1,%2,%3}, {%4,%5,%6,%7}, {%8,%9}, {%0,%1,%2,%3};"
        : "+f"(d[0]), "+f"(d[1]), "+f"(d[2]), "+f"(d[3])
        : "r"(a[0]), "r"(a[1]), "r"(a[2]), "r"(a[3]), "r"(b0), "r"(b1));
}

__device__ __forceinline__ float sigm(float x)  { return 1.0f / (1.0f + __expf(-x)); }
__device__ __forceinline__ float tanhp(float x) { return 2.0f / (1.0f + __expf(-2.0f * x)) - 1.0f; }

// byte offset of h[r][u] inside an A-fragment buffer (bf16)
__device__ __forceinline__ size_t hoff(int r, int u) {
    return (size_t)((((r >> 4) * 32 + (u >> 4)) * 32) + (r & 7) * 4 + ((u & 7) >> 1)) * 16
         + (((r >> 3) & 1) + 2 * ((u >> 3) & 1)) * 4 + (u & 1) * 2;
}

// Replay-safe grid barrier (monotonic generation, counter self-resets).
__device__ __forceinline__ void grid_sync() {
    __syncthreads();
    if (threadIdx.x == 0) {
        __threadfence();
        unsigned cur = g_bar_gen;
        unsigned arr = atomicAdd(&g_bar_cnt, 1u);
        if (arr == NCTA - 1) {
            atomicExch(&g_bar_cnt, 0u);
            __threadfence();
            atomicAdd((unsigned int*)&g_bar_gen, 1u);
        } else {
            while (*(volatile unsigned*)&g_bar_gen == cur) { __nanosleep(32); }
        }
        __threadfence();
    }
    __syncthreads();
}

// LSTM epilogue on D-fragments: even-k-pair lanes own (i,f), partner lanes own (g,o).
template<int NF>
__device__ __forceinline__ void epi(float D[2][NF][4], float* cst, char* hbuf,
                                    int ubase, int mq, int nq, int l) {
    const int gr = l >> 2, tq = l & 3;
    #pragma unroll
    for (int mf = 0; mf < 2; ++mf)
        #pragma unroll
        for (int nf = 0; nf < NF; ++nf) {
            float p0 = __shfl_xor_sync(0xffffffffu, D[mf][nf][0], 1);
            float p1 = __shfl_xor_sync(0xffffffffu, D[mf][nf][1], 1);
            float p2 = __shfl_xor_sync(0xffffffffu, D[mf][nf][2], 1);
            float p3 = __shfl_xor_sync(0xffffffffu, D[mf][nf][3], 1);
            if (!(tq & 1)) {
                int u = ubase + nq * (NF * 2) + nf * 2 + (tq >> 1);
                #pragma unroll
                for (int rh = 0; rh < 2; ++rh) {
                    float gi = rh ? D[mf][nf][2] : D[mf][nf][0];
                    float gf = rh ? D[mf][nf][3] : D[mf][nf][1];
                    float gg = rh ? p2 : p0;
                    float go = rh ? p3 : p1;
                    int s = (mf * NF + nf) * 2 + rh;
                    float c = sigm(gf) * cst[s] + sigm(gi) * tanhp(gg);
                    cst[s] = c;
                    int r = 32 * mq + 16 * mf + 8 * rh + gr;
                    *(__nv_bfloat16*)(hbuf + hoff(r, u)) =
                        __float2bfloat16(sigm(go) * tanhp(c));
                }
            }
        }
}

// =====================================================================
// xform0: g_xg = bias + x @ Wih0^T in per-thread D-fragment layout.
// grid (32 ctas-of-64-cols, TLEN/8); block 256 = 8 warps (4m x 2n). K=64 tf32.
// =====================================================================
#define XW_ST 68
__global__ void __launch_bounds__(NTHR, 1)
xform0(const float* __restrict__ x, const float* __restrict__ Wih,
       const float* __restrict__ bih, const float* __restrict__ bhh)
{
    extern __shared__ float sm[];
    float* Ws = sm;                  // [64][XW_ST]
    float* bs = sm + 64 * XW_ST;

    const int tid = threadIdx.x, l = tid & 31, w = tid >> 5;
    const int gr = l >> 2, tq = l & 3;
    const int mq = w >> 1, nq = w & 1;
    const int cta = blockIdx.x;

    for (int i = tid; i < 64 * 64; i += NTHR) {
        int k = i >> 6, c = i & 63;
        int gate = c & 3, ul = c >> 2;
        int grow = gate * HD + cta * 16 + ul;
        Ws[k * XW_ST + c] = tf32r(Wih[(size_t)grow * DIN + k]);
    }
    if (tid < 64) {
        int gate = tid & 3, ul = tid >> 2;
        int grow = gate * HD + cta * 16 + ul;
        bs[tid] = bih[grow] + bhh[grow];
    }
    __syncthreads();

    for (int tt = 0; tt < 8; ++tt) {
        const int t = blockIdx.y * 8 + tt;
        float D[2][4][4];
        #pragma unroll
        for (int mf = 0; mf < 2; ++mf)
            #pragma unroll
            for (int nf = 0; nf < 4; ++nf) {
                float b0 = bs[nq * 32 + nf * 8 + 2 * tq];
                float b1 = bs[nq * 32 + nf * 8 + 2 * tq + 1];
                D[mf][nf][0] = b0; D[mf][nf][1] = b1;
                D[mf][nf][2] = b0; D[mf][nf][3] = b1;
            }
        #pragma unroll
        for (int kk = 0; kk < 8; ++kk) {
            const int ko = kk * 8;
            uint32_t a[2][4];
            #pragma unroll
            for (int mf = 0; mf < 2; ++mf) {
                int r = 32 * mq + 16 * mf + gr;
                const float* xp = x + (size_t)r * (TLEN * DIN) + (size_t)t * DIN + ko + tq;
                const float* xp8 = xp + (size_t)8 * (TLEN * DIN);
                a[mf][0] = tf32u(xp[0]);  a[mf][1] = tf32u(xp8[0]);
                a[mf][2] = tf32u(xp[4]);  a[mf][3] = tf32u(xp8[4]);
            }
            #pragma unroll
            for (int nf = 0; nf < 4; ++nf) {
                uint32_t b0 = __float_as_uint(Ws[(ko + tq) * XW_ST + nq * 32 + nf * 8 + gr]);
                uint32_t b1 = __float_as_uint(Ws[(ko + tq + 4) * XW_ST + nq * 32 + nf * 8 + gr]);
                mma8(D[0][nf], a[0], b0, b1);
                mma8(D[1][nf], a[1], b0, b1);
            }
        }
        float* dst = g_xg + ((((size_t)t * 32 + cta) * 8 + w) * 8) * 128 + l * 4;
        #pragma unroll
        for (int mf = 0; mf < 2; ++mf)
            #pragma unroll
            for (int nf = 0; nf < 4; ++nf)
                *(float4*)(dst + (mf * 4 + nf) * 128) =
                    make_float4(D[mf][nf][0], D[mf][nf][1], D[mf][nf][2], D[mf][nf][3]);
    }
}

// =====================================================================
// rec: persistent 96 CTAs. CTA<32: layer0 (64 cols, K=512, D-init from xg).
// CTA>=32: layer1 (32 cols, K=1024 = [h0(t); h1(t-1)]), one epoch behind.
// Weights resident in smem in B-fragment layout; A via direct __ldcg LDG.128
// from global bf16 A-fragment h buffers.
// =====================================================================
#define OFF_BIAS 65536
#define SMEM_REC (65536 + 512)

__global__ void __launch_bounds__(NTHR, 1)
rec(const float* __restrict__ Whh0,
    const float* __restrict__ Wih1, const float* __restrict__ Whh1,
    const float* __restrict__ bih1, const float* __restrict__ bhh1,
    const float* __restrict__ fc1w, const float* __restrict__ fc1b,
    const float* __restrict__ fc2w, const float* __restrict__ fc2b,
    float* __restrict__ out)
{
    extern __shared__ char smc[];
    uint4* Wf = (uint4*)smc;
    float* bsm = (float*)(smc + OFF_BIAS);

    const int tid = threadIdx.x, l = tid & 31, w = tid >> 5;
    const int tq = l & 3;
    const int mq = w >> 1, nq = w & 1;
    const int cta = blockIdx.x;
    const bool is0 = (cta < L0CTA);
    const int lc = cta - L0CTA;

    // ---- stage weights into B-fragment smem layout (once) ----
    if (is0) {                                    // NFT=8, K=512, 64 cols
        for (int i = tid; i < 256 * 64; i += NTHR) {
            int c = i & 63, kp = i >> 6, k = kp * 2;
            int gate = c & 3, ul = c >> 2;
            int grow = gate * HD + cta * 16 + ul;
            float w0 = Whh0[(size_t)grow * HD + k];
            float w1 = Whh0[(size_t)grow * HD + k + 1];
            int C = k >> 4, C2 = C >> 1, Codd = C & 1;
            size_t off = ((size_t)(C2 * 8 + (c >> 3)) * 32 + 4 * (c & 7) + (kp & 3)) * 16
                       + (Codd * 2 + ((kp >> 2) & 1)) * 4;
            *(__nv_bfloat162*)(smc + off) =
                __nv_bfloat162(__float2bfloat16(w0), __float2bfloat16(w1));
        }
    } else {                                      // NFT=4, K=1024, 32 cols
        for (int i = tid; i < 512 * 32; i += NTHR) {
            int c = i & 31, kp = i >> 5, k = kp * 2;
            int gate = c & 3, ul = c >> 2;
            int grow = gate * HD + lc * 8 + ul;
            float w0, w1;
            if (k < HD) { w0 = Wih1[(size_t)grow * HD + k];      w1 = Wih1[(size_t)grow * HD + k + 1]; }
            else        { w0 = Whh1[(size_t)grow * HD + k - HD]; w1 = Whh1[(size_t)grow * HD + k - HD + 1]; }
            int C = k >> 4, C2 = C >> 1, Codd = C & 1;
            size_t off = ((size_t)(C2 * 4 + (c >> 3)) * 32 + 4 * (c & 7) + (kp & 3)) * 16
                       + (Codd * 2 + ((kp >> 2) & 1)) * 4;
            *(__nv_bfloat162*)(smc + off) =
                __nv_bfloat162(__float2bfloat16(w0), __float2bfloat16(w1));
        }
        if (tid < 32) {
            int gate = tid & 3, ul = tid >> 2;
            int grow = gate * HD + lc * 8 + ul;
            bsm[tid] = bih1[grow] + bhh1[grow];
        }
    }
    __syncthreads();

    float cst[16];
    #pragma unroll
    for (int s = 0; s < 16; ++s) cst[s] = 0.0f;

    for (int e = 0; e <= TLEN; ++e) {
        if (is0) {
            if (e < TLEN) {
                const uint4* Ab = e ? g_h0f[(e - 1) & 1] : g_zf;
                float D[2][4][4];
                const float* xp = g_xg + ((((size_t)e * 32 + cta) * 8 + w) * 8) * 128 + l * 4;
                #pragma unroll
                for (int mf = 0; mf < 2; ++mf)
                    #pragma unroll
                    for (int nf = 0; nf < 4; ++nf) {
                        float4 v = *(const float4*)(xp + (mf * 4 + nf) * 128);
                        D[mf][nf][0] = v.x; D[mf][nf][1] = v.y;
                        D[mf][nf][2] = v.z; D[mf][nf][3] = v.w;
                    }
                #pragma unroll
                for (int C2 = 0; C2 < 16; ++C2) {
                    uint4 a0 = __ldcg(&Ab[FIDX(2 * mq,     2 * C2,     l)]);
                    uint4 a1 = __ldcg(&Ab[FIDX(2 * mq + 1, 2 * C2,     l)]);
                    uint4 a2 = __ldcg(&Ab[FIDX(2 * mq,     2 * C2 + 1, l)]);
                    uint4 a3 = __ldcg(&Ab[FIDX(2 * mq + 1, 2 * C2 + 1, l)]);
                    #pragma unroll
                    for (int nf = 0; nf < 4; ++nf) {
                        uint4 bq = Wf[(C2 * 8 + nq * 4 + nf) * 32 + l];
                        mma16(D[0][nf], (const uint32_t*)&a0, bq.x, bq.y);
                        mma16(D[1][nf], (const uint32_t*)&a1, bq.x, bq.y);
                        mma16(D[0][nf], (const uint32_t*)&a2, bq.z, bq.w);
                        mma16(D[1][nf], (const uint32_t*)&a3, bq.z, bq.w);
                    }
                }
                epi<4>(D, cst, (char*)g_h0f[e & 1], cta * 16, mq, nq, l);
            }
        } else {
            if (e >= 1) {
                const uint4* A0 = g_h0f[(e - 1) & 1];
                const uint4* A1 = (e >= 2) ? g_h1f[e & 1] : g_zf;
                float D[2][2][4];
                #pragma unroll
                for (int mf = 0; mf < 2; ++mf)
                    #pragma unroll
                    for (int nf = 0; nf < 2; ++nf) {
                        float b0 = bsm[nq * 16 + nf * 8 + 2 * tq];
                        float b1 = bsm[nq * 16 + nf * 8 + 2 * tq + 1];
                        D[mf][nf][0] = b0; D[mf][nf][1] = b1;
                        D[mf][nf][2] = b0; D[mf][nf][3] = b1;
                    }
                #pragma unroll
                for (int C2 = 0; C2 < 16; ++C2) {
                    uint4 a0 = __ldcg(&A0[FIDX(2 * mq,     2 * C2,     l)]);
                    uint4 a1 = __ldcg(&A0[FIDX(2 * mq + 1, 2 * C2,     l)]);
                    uint4 a2 = __ldcg(&A0[FIDX(2 * mq,     2 * C2 + 1, l)]);
                    uint4 a3 = __ldcg(&A0[FIDX(2 * mq + 1, 2 * C2 + 1, l)]);
                    #pragma unroll
                    for (int nf = 0; nf < 2; ++nf) {
                        uint4 bq = Wf[(C2 * 4 + nq * 2 + nf) * 32 + l];
                        mma16(D[0][nf], (const uint32_t*)&a0, bq.x, bq.y);
                        mma16(D[1][nf], (const uint32_t*)&a1, bq.x, bq.y);
                        mma16(D[0][nf], (const uint32_t*)&a2, bq.z, bq.w);
                        mma16(D[1][nf], (const uint32_t*)&a3, bq.z, bq.w);
                    }
                }
                #pragma unroll
                for (int C2 = 0; C2 < 16; ++C2) {
                    uint4 a0 = __ldcg(&A1[FIDX(2 * mq,     2 * C2,     l)]);
                    uint4 a1 = __ldcg(&A1[FIDX(2 * mq + 1, 2 * C2,     l)]);
                    uint4 a2 = __ldcg(&A1[FIDX(2 * mq,     2 * C2 + 1, l)]);
                    uint4 a3 = __ldcg(&A1[FIDX(2 * mq + 1, 2 * C2 + 1, l)]);
                    #pragma unroll
                    for (int nf = 0; nf < 2; ++nf) {
                        uint4 bq = Wf[((C2 + 16) * 4 + nq * 2 + nf) * 32 + l];
                        mma16(D[0][nf], (const uint32_t*)&a0, bq.x, bq.y);
                        mma16(D[1][nf], (const uint32_t*)&a1, bq.x, bq.y);
                        mma16(D[0][nf], (const uint32_t*)&a2, bq.z, bq.w);
                        mma16(D[1][nf], (const uint32_t*)&a3, bq.z, bq.w);
                    }
                }
                epi<2>(D, cst, (char*)g_h1f[(e - 1) & 1], lc * 8, mq, nq, l);
            }
        }
        grid_sync();
    }

    // ---------------- FC head on CTA 0 ----------------
    if (cta == 0) {
        float* sw = (float*)smc;      // reuse weight region
        for (int i = tid; i < HD * 32; i += NTHR) {
            int u = i >> 5, j = i & 31;
            sw[i] = fc1w[(size_t)j * HD + u];
        }
        __syncthreads();
        if (tid < BSZ) {
            const uint4* hb = g_h1f[(TLEN - 1) & 1];
            float s[32];
            #pragma unroll
            for (int j = 0; j < 32; ++j) s[j] = 0.0f;
            for (int u = 0; u < HD; ++u) {
                uint4 q = __ldcg(&hb[FIDX(tid >> 4, u >> 4, (tid & 7) * 4 + ((u & 7) >> 1))]);
                uint32_t rg = ((const uint32_t*)&q)[((tid >> 3) & 1) + 2 * ((u >> 3) & 1)];
                float v = __bfloat162float(((const __nv_bfloat16*)&rg)[u & 1]);
                const float4* ww = (const float4*)(sw + u * 32);
                #pragma unroll
                for (int j4 = 0; j4 < 8; ++j4) {
                    float4 wv = ww[j4];
                    s[4 * j4 + 0] += v * wv.x;
                    s[4 * j4 + 1] += v * wv.y;
                    s[4 * j4 + 2] += v * wv.z;
                    s[4 * j4 + 3] += v * wv.w;
                }
            }
            float y = fc2b[0];
            #pragma unroll
            for (int j = 0; j < 32; ++j) y += fc2w[j] * (s[j] + fc1b[j]);
            out[tid] = y;
        }
    }
}

// =====================================================================
extern "C" void kernel_launch(void* const* d_in, const int* in_sizes, int n_in,
                              void* d_out, int out_size)
{
    (void)in_sizes; (void)n_in; (void)out_size;
    const float* x    = (const float*)d_in[0];
    const float* Wih0 = (const float*)d_in[1];
    const float* Whh0 = (const float*)d_in[2];
    const float* bih0 = (const float*)d_in[3];
    const float* bhh0 = (const float*)d_in[4];
    const float* Wih1 = (const float*)d_in[5];
    const float* Whh1 = (const float*)d_in[6];
    const float* bih1 = (const float*)d_in[7];
    const float* bhh1 = (const float*)d_in[8];
    const float* fc1w = (const float*)d_in[9];
    const float* fc1b = (const float*)d_in[10];
    const float* fc2w = (const float*)d_in[11];
    const float* fc2b = (const float*)d_in[12];
    float* out = (float*)d_out;

    const int sm_x = 64 * XW_ST * 4 + 256;
    cudaFuncSetAttribute(xform0, cudaFuncAttributeMaxDynamicSharedMemorySize, sm_x);
    cudaFuncSetAttribute(rec,    cudaFuncAttributeMaxDynamicSharedMemorySize, SMEM_REC);

    xform0<<<dim3(L0CTA, TLEN / 8), NTHR, sm_x>>>(x, Wih0, bih0, bhh0);
    rec<<<NCTA, NTHR, SMEM_REC>>>(Whh0, Wih1, Whh1, bih1, bhh1,
                                  fc1w, fc1b, fc2w, fc2b, out);
}

// round 8
// speedup vs baseline: 3.9163x; 1.1955x over previous
#include <cuda_runtime.h>
#include <cuda_bf16.h>
#include <cstdint>

#define TLEN 1024
#define BSZ  128
#define DIN  64
#define HD   512
#define N0CTA 64
#define N1CTA 64
#define NALL  128
#define NTHR  256

// fragment index: uint4 element for (16-row block R, 16-k block C, lane l)
#define FIDX(R, C, l) ((((R) * 32 + (C)) * 32) + (l))

// ---------------- device scratch (static, no allocations) ----------------
__device__ float g_xg[268435456];          // 1 GB: L0 xg frags [t][cta][w][mf*2+nf][l][4]
__device__ uint4 g_h0f[8][8192];           // h0 bf16 A-frag ring (8 deep, 128 KB each)
__device__ uint4 g_h1f[2][8192];           // h1 double buffer
__device__ uint4 g_zf[8192];               // stays zero
__device__ unsigned g_cnt0, g_cnt1, g_fin;
__device__ volatile unsigned g_gen0, g_gen1;

// ---------------- helpers ----------------
__device__ __forceinline__ uint32_t tf32u(float x) {
    uint32_t u; asm("cvt.rna.tf32.f32 %0, %1;" : "=r"(u) : "f"(x)); return u;
}
__device__ __forceinline__ float tf32r(float x) { return __uint_as_float(tf32u(x)); }

__device__ __forceinline__ void mma8(float d[4], const uint32_t a[4], uint32_t b0, uint32_t b1) {
    asm volatile("mma.sync.aligned.m16n8k8.row.col.f32.tf32.tf32.f32 "
        "{%0,%1,%2,%3}, {%4,%5,%6,%7}, {%8,%9}, {%0,%1,%2,%3};"
        : "+f"(d[0]), "+f"(d[1]), "+f"(d[2]), "+f"(d[3])
        : "r"(a[0]), "r"(a[1]), "r"(a[2]), "r"(a[3]), "r"(b0), "r"(b1));
}
__device__ __forceinline__ void mma16(float d[4], const uint32_t* a, uint32_t b0, uint32_t b1) {
    asm volatile("mma.sync.aligned.m16n8k16.row.col.f32.bf16.bf16.f32 "
        "{%0,%1,%2,%3}, {%4,%5,%6,%7}, {%8,%9}, {%0,%1,%2,%3};"
        : "+f"(d[0]), "+f"(d[1]), "+f"(d[2]), "+f"(d[3])
        : "r"(a[0]), "r"(a[1]), "r"(a[2]), "r"(a[3]), "r"(b0), "r"(b1));
}

__device__ __forceinline__ float sigm(float x)  { return 1.0f / (1.0f + __expf(-x)); }
__device__ __forceinline__ float tanhp(float x) { return 2.0f / (1.0f + __expf(-2.0f * x)) - 1.0f; }

// byte offset of h[r][u] inside an A-fragment buffer (bf16)
__device__ __forceinline__ size_t hoff(int r, int u) {
    return (size_t)((((r >> 4) * 32 + (u >> 4)) * 32) + (r & 7) * 4 + ((u & 7) >> 1)) * 16
         + (((r >> 3) & 1) + 2 * ((u >> 3) & 1)) * 4 + (u & 1) * 2;
}

// wait until *gen >= target (tid 0 spins; block-wide acquire via syncthreads)
__device__ __forceinline__ void wait_ge(volatile unsigned* gen, unsigned target) {
    if (threadIdx.x == 0) {
        while (*gen < target) { }
        __threadfence();
    }
    __syncthreads();
}

// group barrier: counter self-resets; gen increments monotonically (reset at kernel end)
__device__ __forceinline__ void group_sync(unsigned* cnt, volatile unsigned* gen,
                                           unsigned n, unsigned target) {
    __syncthreads();
    if (threadIdx.x == 0) {
        __threadfence();
        if (atomicAdd(cnt, 1u) == n - 1) {
            atomicExch(cnt, 0u);
            __threadfence();
            atomicAdd((unsigned*)gen, 1u);
        } else {
            while (*gen < target) { }
        }
        __threadfence();
    }
    __syncthreads();
}

// balanced LSTM epilogue: even-tq lane handles row gr, odd lane row gr+8
__device__ __forceinline__ void epi2(float D[2][2][4], float* cst, char* hbuf,
                                     int ubase, int mq, int nq, int gr, int tq) {
    const bool odd = tq & 1;
    #pragma unroll
    for (int mf = 0; mf < 2; ++mf)
        #pragma unroll
        for (int nf = 0; nf < 2; ++nf) {
            float d0 = D[mf][nf][0], d1 = D[mf][nf][1];
            float d2 = D[mf][nf][2], d3 = D[mf][nf][3];
            float p0 = __shfl_xor_sync(0xffffffffu, d0, 1);
            float p1 = __shfl_xor_sync(0xffffffffu, d1, 1);
            float p2 = __shfl_xor_sync(0xffffffffu, d2, 1);
            float p3 = __shfl_xor_sync(0xffffffffu, d3, 1);
            float gi = odd ? p2 : d0;
            float gf = odd ? p3 : d1;
            float gg = odd ? d2 : p0;
            float go = odd ? d3 : p1;
            int s = mf * 2 + nf;
            float c = sigm(gf) * cst[s] + sigm(gi) * tanhp(gg);
            cst[s] = c;
            float h = sigm(go) * tanhp(c);
            int r = 32 * mq + 16 * mf + gr + (odd ? 8 : 0);
            int u = ubase + nq * 4 + nf * 2 + (tq >> 1);
            *(__nv_bfloat16*)(hbuf + hoff(r, u)) = __float2bfloat16(h);
        }
}

// =====================================================================
// xform0: g_xg = bias + x @ Wih0^T in per-thread D-fragment layout.
// grid (64 col-groups of 32 cols, TLEN/8); 8 warps = 4m x 2n. K=64 tf32.
// =====================================================================
#define XW_ST 36
__global__ void __launch_bounds__(NTHR, 1)
xform0(const float* __restrict__ x, const float* __restrict__ Wih,
       const float* __restrict__ bih, const float* __restrict__ bhh)
{
    extern __shared__ float sm[];
    float* Ws = sm;                  // [64][XW_ST]
    float* bs = sm + 64 * XW_ST;

    const int tid = threadIdx.x, l = tid & 31, w = tid >> 5;
    const int gr = l >> 2, tq = l & 3;
    const int mq = w >> 1, nq = w & 1;
    const int cta = blockIdx.x;

    for (int i = tid; i < 64 * 32; i += NTHR) {
        int k = i >> 5, c = i & 31;
        int gate = c & 3, ul = c >> 2;
        int grow = gate * HD + cta * 8 + ul;
        Ws[k * XW_ST + c] = tf32r(Wih[(size_t)grow * DIN + k]);
    }
    if (tid < 32) {
        int gate = tid & 3, ul = tid >> 2;
        int grow = gate * HD + cta * 8 + ul;
        bs[tid] = bih[grow] + bhh[grow];
    }
    __syncthreads();

    for (int tt = 0; tt < 8; ++tt) {
        const int t = blockIdx.y * 8 + tt;
        float D[2][2][4];
        #pragma unroll
        for (int mf = 0; mf < 2; ++mf)
            #pragma unroll
            for (int nf = 0; nf < 2; ++nf) {
                float b0 = bs[nq * 16 + nf * 8 + 2 * tq];
                float b1 = bs[nq * 16 + nf * 8 + 2 * tq + 1];
                D[mf][nf][0] = b0; D[mf][nf][1] = b1;
                D[mf][nf][2] = b0; D[mf][nf][3] = b1;
            }
        #pragma unroll
        for (int kk = 0; kk < 8; ++kk) {
            const int ko = kk * 8;
            uint32_t a[2][4];
            #pragma unroll
            for (int mf = 0; mf < 2; ++mf) {
                int r = 32 * mq + 16 * mf + gr;
                const float* xp  = x + (size_t)r * (TLEN * DIN) + (size_t)t * DIN + ko + tq;
                const float* xp8 = xp + (size_t)8 * (TLEN * DIN);
                a[mf][0] = tf32u(xp[0]);  a[mf][1] = tf32u(xp8[0]);
                a[mf][2] = tf32u(xp[4]);  a[mf][3] = tf32u(xp8[4]);
            }
            #pragma unroll
            for (int nf = 0; nf < 2; ++nf) {
                uint32_t b0 = __float_as_uint(Ws[(ko + tq) * XW_ST + nq * 16 + nf * 8 + gr]);
                uint32_t b1 = __float_as_uint(Ws[(ko + tq + 4) * XW_ST + nq * 16 + nf * 8 + gr]);
                mma8(D[0][nf], a[0], b0, b1);
                mma8(D[1][nf], a[1], b0, b1);
            }
        }
        float* dst = g_xg + ((((size_t)t * N0CTA + cta) * 8 + w) * 4) * 128 + l * 4;
        #pragma unroll
        for (int mf = 0; mf < 2; ++mf)
            #pragma unroll
            for (int nf = 0; nf < 2; ++nf)
                *(float4*)(dst + (mf * 2 + nf) * 128) =
                    make_float4(D[mf][nf][0], D[mf][nf][1], D[mf][nf][2], D[mf][nf][3]);
    }
}

// =====================================================================
// rec: 128 persistent CTAs in two decoupled groups.
//   CTA 0..63   : layer0, 32 cols, K=512 (h0[t-1]), D-init from xg (epilogue add)
//   CTA 64..127 : layer1, 32 cols, K=1024 = [h0(t); h1(t-1)], trails via gen0
// =====================================================================
#define OFF_BIAS 65536
#define SMEM_REC (OFF_BIAS + 512)

__global__ void __launch_bounds__(NTHR, 1)
rec(const float* __restrict__ Whh0,
    const float* __restrict__ Wih1, const float* __restrict__ Whh1,
    const float* __restrict__ bih1, const float* __restrict__ bhh1,
    const float* __restrict__ fc1w, const float* __restrict__ fc1b,
    const float* __restrict__ fc2w, const float* __restrict__ fc2b,
    float* __restrict__ out)
{
    extern __shared__ char smc[];
    uint4* Wf = (uint4*)smc;
    float* bsm = (float*)(smc + OFF_BIAS);

    const int tid = threadIdx.x, l = tid & 31, w = tid >> 5;
    const int gr = l >> 2, tq = l & 3;
    const int mq = w >> 1, nq = w & 1;
    const int cta = blockIdx.x;
    const bool is0 = (cta < N0CTA);
    const int lc = is0 ? cta : (cta - N0CTA);

    // ---- stage weights into B-fragment smem layout (once) ----
    {
        const int nkp = is0 ? 256 : 512;    // k-pairs
        for (int i = tid; i < nkp * 32; i += NTHR) {
            int c = i & 31, kp = i >> 5, k = kp * 2;
            int gate = c & 3, ul = c >> 2;
            int grow = gate * HD + lc * 8 + ul;
            float w0, w1;
            if (is0)        { w0 = Whh0[(size_t)grow * HD + k];      w1 = Whh0[(size_t)grow * HD + k + 1]; }
            else if (k < HD){ w0 = Wih1[(size_t)grow * HD + k];      w1 = Wih1[(size_t)grow * HD + k + 1]; }
            else            { w0 = Whh1[(size_t)grow * HD + k - HD]; w1 = Whh1[(size_t)grow * HD + k - HD + 1]; }
            int C = k >> 4, C2 = C >> 1, Codd = C & 1;
            size_t off = ((size_t)(C2 * 4 + (c >> 3)) * 32 + 4 * (c & 7) + (kp & 3)) * 16
                       + (Codd * 2 + ((kp >> 2) & 1)) * 4;
            *(__nv_bfloat162*)(smc + off) =
                __nv_bfloat162(__float2bfloat16(w0), __float2bfloat16(w1));
        }
        if (!is0 && tid < 32) {
            int gate = tid & 3, ul = tid >> 2;
            int grow = gate * HD + lc * 8 + ul;
            bsm[tid] = bih1[grow] + bhh1[grow];
        }
    }
    __syncthreads();

    float cst[4] = {0.0f, 0.0f, 0.0f, 0.0f};

    if (is0) {
        // ================= layer 0 group =================
        for (int e = 0; e < TLEN; ++e) {
            // xg loads (streaming; consumed in epilogue)
            const float* xp = g_xg + ((((size_t)e * N0CTA + cta) * 8 + w) * 4) * 128 + l * 4;
            float4 xv[4];
            #pragma unroll
            for (int f = 0; f < 4; ++f) xv[f] = __ldcs((const float4*)(xp + f * 128));

            const uint4* Ab = e ? g_h0f[(e - 1) & 7] : g_zf;
            float D[2][2][4];
            #pragma unroll
            for (int mf = 0; mf < 2; ++mf)
                #pragma unroll
                for (int nf = 0; nf < 2; ++nf)
                    #pragma unroll
                    for (int q = 0; q < 4; ++q) D[mf][nf][q] = 0.0f;

            uint4 ab[4][4];
            #pragma unroll
            for (int p = 0; p < 4; ++p) {
                ab[p][0] = __ldcg(&Ab[FIDX(2 * mq,     2 * p,     l)]);
                ab[p][1] = __ldcg(&Ab[FIDX(2 * mq + 1, 2 * p,     l)]);
                ab[p][2] = __ldcg(&Ab[FIDX(2 * mq,     2 * p + 1, l)]);
                ab[p][3] = __ldcg(&Ab[FIDX(2 * mq + 1, 2 * p + 1, l)]);
            }
            #pragma unroll
            for (int C2 = 0; C2 < 16; ++C2) {
                const int s = C2 & 3;
                uint4 a0 = ab[s][0], a1 = ab[s][1], a2 = ab[s][2], a3 = ab[s][3];
                if (C2 + 4 < 16) {
                    const int c = C2 + 4;
                    ab[s][0] = __ldcg(&Ab[FIDX(2 * mq,     2 * c,     l)]);
                    ab[s][1] = __ldcg(&Ab[FIDX(2 * mq + 1, 2 * c,     l)]);
                    ab[s][2] = __ldcg(&Ab[FIDX(2 * mq,     2 * c + 1, l)]);
                    ab[s][3] = __ldcg(&Ab[FIDX(2 * mq + 1, 2 * c + 1, l)]);
                }
                uint4 bq0 = Wf[(C2 * 4 + nq * 2 + 0) * 32 + l];
                uint4 bq1 = Wf[(C2 * 4 + nq * 2 + 1) * 32 + l];
                mma16(D[0][0], (const uint32_t*)&a0, bq0.x, bq0.y);
                mma16(D[1][0], (const uint32_t*)&a1, bq0.x, bq0.y);
                mma16(D[0][0], (const uint32_t*)&a2, bq0.z, bq0.w);
                mma16(D[1][0], (const uint32_t*)&a3, bq0.z, bq0.w);
                mma16(D[0][1], (const uint32_t*)&a0, bq1.x, bq1.y);
                mma16(D[1][1], (const uint32_t*)&a1, bq1.x, bq1.y);
                mma16(D[0][1], (const uint32_t*)&a2, bq1.z, bq1.w);
                mma16(D[1][1], (const uint32_t*)&a3, bq1.z, bq1.w);
            }

            // ring back-pressure: h0[e & 7] overwrites h0[e-8]; L1 epoch e-7 must be done
            if (e >= 8) wait_ge(&g_gen1, (unsigned)(e - 7));

            #pragma unroll
            for (int mf = 0; mf < 2; ++mf)
                #pragma unroll
                for (int nf = 0; nf < 2; ++nf)
                    #pragma unroll
                    for (int q = 0; q < 4; ++q)
                        D[mf][nf][q] += (&xv[mf * 2 + nf].x)[q];

            epi2(D, cst, (char*)g_h0f[e & 7], cta * 8, mq, nq, gr, tq);
            group_sync(&g_cnt0, &g_gen0, N0CTA, (unsigned)(e + 1));
        }
    } else {
        // ================= layer 1 group (trails L0) =================
        for (int e = 1; e <= TLEN; ++e) {
            wait_ge(&g_gen0, (unsigned)e);          // h0[e-1] published
            const uint4* A0 = g_h0f[(e - 1) & 7];
            const uint4* A1 = (e >= 2) ? g_h1f[e & 1] : g_zf;

            float D[2][2][4];
            #pragma unroll
            for (int mf = 0; mf < 2; ++mf)
                #pragma unroll
                for (int nf = 0; nf < 2; ++nf)
                    #pragma unroll
                    for (int q = 0; q < 4; ++q) D[mf][nf][q] = 0.0f;

            uint4 ab[4][4];
            #pragma unroll
            for (int p = 0; p < 4; ++p) {
                ab[p][0] = __ldcg(&A0[FIDX(2 * mq,     2 * p,     l)]);
                ab[p][1] = __ldcg(&A0[FIDX(2 * mq + 1, 2 * p,     l)]);
                ab[p][2] = __ldcg(&A0[FIDX(2 * mq,     2 * p + 1, l)]);
                ab[p][3] = __ldcg(&A0[FIDX(2 * mq + 1, 2 * p + 1, l)]);
            }
            #pragma unroll
            for (int C2 = 0; C2 < 32; ++C2) {
                const int s = C2 & 3;
                uint4 a0 = ab[s][0], a1 = ab[s][1], a2 = ab[s][2], a3 = ab[s][3];
                if (C2 + 4 < 32) {
                    const int cg = C2 + 4;
                    const uint4* S = (cg < 16) ? A0 : A1;
                    const int c = cg & 15;
                    ab[s][0] = __ldcg(&S[FIDX(2 * mq,     2 * c,     l)]);
                    ab[s][1] = __ldcg(&S[FIDX(2 * mq + 1, 2 * c,     l)]);
                    ab[s][2] = __ldcg(&S[FIDX(2 * mq,     2 * c + 1, l)]);
                    ab[s][3] = __ldcg(&S[FIDX(2 * mq + 1, 2 * c + 1, l)]);
                }
                uint4 bq0 = Wf[(C2 * 4 + nq * 2 + 0) * 32 + l];
                uint4 bq1 = Wf[(C2 * 4 + nq * 2 + 1) * 32 + l];
                mma16(D[0][0], (const uint32_t*)&a0, bq0.x, bq0.y);
                mma16(D[1][0], (const uint32_t*)&a1, bq0.x, bq0.y);
                mma16(D[0][0], (const uint32_t*)&a2, bq0.z, bq0.w);
                mma16(D[1][0], (const uint32_t*)&a3, bq0.z, bq0.w);
                mma16(D[0][1], (const uint32_t*)&a0, bq1.x, bq1.y);
                mma16(D[1][1], (const uint32_t*)&a1, bq1.x, bq1.y);
                mma16(D[0][1], (const uint32_t*)&a2, bq1.z, bq1.w);
                mma16(D[1][1], (const uint32_t*)&a3, bq1.z, bq1.w);
            }

            #pragma unroll
            for (int mf = 0; mf < 2; ++mf)
                #pragma unroll
                for (int nf = 0; nf < 2; ++nf)
                    #pragma unroll
                    for (int q = 0; q < 4; ++q)
                        D[mf][nf][q] += bsm[(nq * 2 + nf) * 8 + 2 * tq + (q & 1)];

            epi2(D, cst, (char*)g_h1f[(e - 1) & 1], lc * 8, mq, nq, gr, tq);
            group_sync(&g_cnt1, &g_gen1, N1CTA, (unsigned)e);
        }
    }

    // ---------------- FC head on CTA 0 ----------------
    if (cta == 0) {
        wait_ge(&g_gen1, (unsigned)TLEN);           // all of h1 published
        float* sw = (float*)smc;                    // reuse weight region
        for (int i = tid; i < HD * 32; i += NTHR) {
            int u = i >> 5, j = i & 31;
            sw[i] = fc1w[(size_t)j * HD + u];
        }
        __syncthreads();
        if (tid < BSZ) {
            const uint4* hb = g_h1f[(TLEN - 1) & 1];
            float s[32];
            #pragma unroll
            for (int j = 0; j < 32; ++j) s[j] = 0.0f;
            for (int u = 0; u < HD; ++u) {
                uint4 q = __ldcg(&hb[FIDX(tid >> 4, u >> 4, (tid & 7) * 4 + ((u & 7) >> 1))]);
                uint32_t rg = ((const uint32_t*)&q)[((tid >> 3) & 1) + 2 * ((u >> 3) & 1)];
                float v = __bfloat162float(((const __nv_bfloat16*)&rg)[u & 1]);
                const float4* ww = (const float4*)(sw + u * 32);
                #pragma unroll
                for (int j4 = 0; j4 < 8; ++j4) {
                    float4 wv = ww[j4];
                    s[4 * j4 + 0] += v * wv.x;
                    s[4 * j4 + 1] += v * wv.y;
                    s[4 * j4 + 2] += v * wv.z;
                    s[4 * j4 + 3] += v * wv.w;
                }
            }
            float y = fc2b[0];
            #pragma unroll
            for (int j = 0; j < 32; ++j) y += fc2w[j] * (s[j] + fc1b[j]);
            out[tid] = y;
        }
        __syncthreads();
    }

    // ---------------- finalize: reset counters for graph replay ----------------
    __syncthreads();
    __threadfence();
    if (tid == 0) {
        if (atomicAdd(&g_fin, 1u) == NALL - 1) {
            g_gen0 = 0;
            g_gen1 = 0;
            __threadfence();
            atomicExch(&g_fin, 0u);
        }
    }
}

// =====================================================================
extern "C" void kernel_launch(void* const* d_in, const int* in_sizes, int n_in,
                              void* d_out, int out_size)
{
    (void)in_sizes; (void)n_in; (void)out_size;
    const float* x    = (const float*)d_in[0];
    const float* Wih0 = (const float*)d_in[1];
    const float* Whh0 = (const float*)d_in[2];
    const float* bih0 = (const float*)d_in[3];
    const float* bhh0 = (const float*)d_in[4];
    const float* Wih1 = (const float*)d_in[5];
    const float* Whh1 = (const float*)d_in[6];
    const float* bih1 = (const float*)d_in[7];
    const float* bhh1 = (const float*)d_in[8];
    const float* fc1w = (const float*)d_in[9];
    const float* fc1b = (const float*)d_in[10];
    const float* fc2w = (const float*)d_in[11];
    const float* fc2b = (const float*)d_in[12];
    float* out = (float*)d_out;

    const int sm_x = 64 * XW_ST * 4 + 256;
    cudaFuncSetAttribute(xform0, cudaFuncAttributeMaxDynamicSharedMemorySize, sm_x);
    cudaFuncSetAttribute(rec,    cudaFuncAttributeMaxDynamicSharedMemorySize, SMEM_REC);

    xform0<<<dim3(N0CTA, TLEN / 8), NTHR, sm_x>>>(x, Wih0, bih0, bhh0);
    rec<<<NALL, NTHR, SMEM_REC>>>(Whh0, Wih1, Whh1, bih1, bhh1,
                                  fc1w, fc1b, fc2w, fc2b, out);
}

// round 9
// speedup vs baseline: 4.2606x; 1.0879x over previous
#include <cuda_runtime.h>
#include <cuda_bf16.h>
#include <cstdint>

#define TLEN 1024
#define BSZ  128
#define DIN  64
#define HD   512
#define N0CTA 64
#define N1CTA 64
#define NALL  128
#define NTHR  256

// fragment index: uint4 element for (16-row block R, 16-k block C, lane l)
#define FIDX(R, C, l) ((((R) * 32 + (C)) * 32) + (l))

// ---------------- device scratch (static, no allocations) ----------------
__device__ float g_xg[268435456];          // 1 GB: L0 xg frags [t][cta][w][nf][l][4]
__device__ uint4 g_h0f[8][8192];           // h0 bf16 A-frag ring (8 deep)
__device__ uint4 g_h1f[2][8192];           // h1 double buffer
__device__ uint4 g_zf[8192];               // stays zero
__device__ unsigned g_cnt0, g_cnt1, g_fin;
__device__ volatile unsigned g_gen0, g_gen1;

// ---------------- helpers ----------------
__device__ __forceinline__ uint32_t tf32u(float x) {
    uint32_t u; asm("cvt.rna.tf32.f32 %0, %1;" : "=r"(u) : "f"(x)); return u;
}
__device__ __forceinline__ float tf32r(float x) { return __uint_as_float(tf32u(x)); }

__device__ __forceinline__ void mma8(float d[4], const uint32_t a[4], uint32_t b0, uint32_t b1) {
    asm volatile("mma.sync.aligned.m16n8k8.row.col.f32.tf32.tf32.f32 "
        "{%0,%1,%2,%3}, {%4,%5,%6,%7}, {%8,%9}, {%0,%1,%2,%3};"
        : "+f"(d[0]), "+f"(d[1]), "+f"(d[2]), "+f"(d[3])
        : "r"(a[0]), "r"(a[1]), "r"(a[2]), "r"(a[3]), "r"(b0), "r"(b1));
}
__device__ __forceinline__ void mma16(float d[4], const uint32_t* a, uint32_t b0, uint32_t b1) {
    asm volatile("mma.sync.aligned.m16n8k16.row.col.f32.bf16.bf16.f32 "
        "{%0,%1,%2,%3}, {%4,%5,%6,%7}, {%8,%9}, {%0,%1,%2,%3};"
        : "+f"(d[0]), "+f"(d[1]), "+f"(d[2]), "+f"(d[3])
        : "r"(a[0]), "r"(a[1]), "r"(a[2]), "r"(a[3]), "r"(b0), "r"(b1));
}

__device__ __forceinline__ float sigm(float x)  { return 1.0f / (1.0f + __expf(-x)); }
__device__ __forceinline__ float tanhp(float x) { return 2.0f / (1.0f + __expf(-2.0f * x)) - 1.0f; }

// wait until *gen >= target
__device__ __forceinline__ void wait_ge(volatile unsigned* gen, unsigned target) {
    if (threadIdx.x == 0) {
        while (*gen < target) { }
        __threadfence();
    }
    __syncthreads();
}

// group barrier: counter self-resets; gen increments monotonically (reset at kernel end)
__device__ __forceinline__ void group_sync(unsigned* cnt, volatile unsigned* gen,
                                           unsigned n, unsigned target) {
    __syncthreads();
    if (threadIdx.x == 0) {
        __threadfence();
        if (atomicAdd(cnt, 1u) == n - 1) {
            atomicExch(cnt, 0u);
            __threadfence();
            atomicAdd((unsigned*)gen, 1u);
        } else {
            while (*gen < target) { }
        }
        __threadfence();
    }
    __syncthreads();
}

// LSTM epilogue, 8x1 tiling. Lane roles per nf:
//   even-tq lane owns gates (i,f), odd-tq gates (g,o); xor-1 exchange, even lane
//   computes row r0=16w+gr, odd lane row r0+8. xor-2 packs bf16x2 (unit u, u+1).
__device__ __forceinline__ void epi8(float D[4][4], float* cst, char* hbuf,
                                     int ubase, int w, int l) {
    const int gr = l >> 2, tq = l & 3;
    const bool odd = tq & 1;
    const int row = 16 * w + gr + (odd ? 8 : 0);
    #pragma unroll
    for (int nf = 0; nf < 4; ++nf) {
        float d0 = D[nf][0], d1 = D[nf][1], d2 = D[nf][2], d3 = D[nf][3];
        float p0 = __shfl_xor_sync(0xffffffffu, d0, 1);
        float p1 = __shfl_xor_sync(0xffffffffu, d1, 1);
        float p2 = __shfl_xor_sync(0xffffffffu, d2, 1);
        float p3 = __shfl_xor_sync(0xffffffffu, d3, 1);
        float gi = odd ? p2 : d0;
        float gf = odd ? p3 : d1;
        float gg = odd ? d2 : p0;
        float go = odd ? d3 : p1;
        float c = sigm(gf) * cst[nf] + sigm(gi) * tanhp(gg);
        cst[nf] = c;
        float h = sigm(go) * tanhp(c);
        float hp = __shfl_xor_sync(0xffffffffu, h, 2);
        if (!(tq & 2)) {                       // owns even unit; partner has u+1
            int u = ubase + nf * 2;
            __nv_bfloat162 pk(__float2bfloat16(h), __float2bfloat16(hp));
            size_t off = (size_t)(((w * 32 + (u >> 4)) * 32) + gr * 4 + nf) * 16
                       + ((odd ? 1 : 0) + 2 * ((u >> 3) & 1)) * 4;
            *(uint32_t*)(hbuf + off) = *(uint32_t*)&pk;
        }
    }
}

// =====================================================================
// xform0: g_xg = bias + x @ Wih0^T in per-thread D-fragment layout (8x1 tiling).
// grid (64 col-groups of 32 cols, TLEN/8); warp w owns rows 16w..16w+15. K=64 tf32.
// =====================================================================
#define XW_ST 36
__global__ void __launch_bounds__(NTHR, 1)
xform0(const float* __restrict__ x, const float* __restrict__ Wih,
       const float* __restrict__ bih, const float* __restrict__ bhh)
{
    extern __shared__ float sm[];
    float* Ws = sm;                  // [64][XW_ST]
    float* bs = sm + 64 * XW_ST;

    const int tid = threadIdx.x, l = tid & 31, w = tid >> 5;
    const int gr = l >> 2, tq = l & 3;
    const int cta = blockIdx.x;

    for (int i = tid; i < 64 * 32; i += NTHR) {
        int k = i >> 5, c = i & 31;
        int gate = c & 3, ul = c >> 2;
        int grow = gate * HD + cta * 8 + ul;
        Ws[k * XW_ST + c] = tf32r(Wih[(size_t)grow * DIN + k]);
    }
    if (tid < 32) {
        int gate = tid & 3, ul = tid >> 2;
        int grow = gate * HD + cta * 8 + ul;
        bs[tid] = bih[grow] + bhh[grow];
    }
    __syncthreads();

    const int r0 = 16 * w + gr;
    for (int tt = 0; tt < 8; ++tt) {
        const int t = blockIdx.y * 8 + tt;
        float D[4][4];
        #pragma unroll
        for (int nf = 0; nf < 4; ++nf) {
            float b0 = bs[nf * 8 + 2 * tq];
            float b1 = bs[nf * 8 + 2 * tq + 1];
            D[nf][0] = b0; D[nf][1] = b1; D[nf][2] = b0; D[nf][3] = b1;
        }
        #pragma unroll
        for (int kk = 0; kk < 8; ++kk) {
            const int ko = kk * 8;
            const float* xp  = x + (size_t)r0 * (TLEN * DIN) + (size_t)t * DIN + ko + tq;
            const float* xp8 = xp + (size_t)8 * (TLEN * DIN);
            uint32_t a[4] = { tf32u(xp[0]), tf32u(xp8[0]), tf32u(xp[4]), tf32u(xp8[4]) };
            #pragma unroll
            for (int nf = 0; nf < 4; ++nf) {
                uint32_t b0 = __float_as_uint(Ws[(ko + tq) * XW_ST + nf * 8 + gr]);
                uint32_t b1 = __float_as_uint(Ws[(ko + tq + 4) * XW_ST + nf * 8 + gr]);
                mma8(D[nf], a, b0, b1);
            }
        }
        float* dst = g_xg + ((((size_t)t * N0CTA + cta) * 8 + w) * 4) * 128 + l * 4;
        #pragma unroll
        for (int nf = 0; nf < 4; ++nf)
            *(float4*)(dst + nf * 128) = make_float4(D[nf][0], D[nf][1], D[nf][2], D[nf][3]);
    }
}

// =====================================================================
// rec: 128 persistent CTAs, two decoupled groups (private barriers + gen counters).
//   CTA 0..63   : layer0, 32 cols, K=512 (h0[t-1]), xg added in epilogue
//   CTA 64..127 : layer1, 32 cols, K=1024 = [h0(t); h1(t-1)], trails gen0
// Warp w owns rows 16w..16w+15 — each h row loaded exactly once per CTA.
// =====================================================================
#define OFF_BIAS 65536
#define SMEM_REC (OFF_BIAS + 512)

__global__ void __launch_bounds__(NTHR, 1)
rec(const float* __restrict__ Whh0,
    const float* __restrict__ Wih1, const float* __restrict__ Whh1,
    const float* __restrict__ bih1, const float* __restrict__ bhh1,
    const float* __restrict__ fc1w, const float* __restrict__ fc1b,
    const float* __restrict__ fc2w, const float* __restrict__ fc2b,
    float* __restrict__ out)
{
    extern __shared__ char smc[];
    uint4* Wf = (uint4*)smc;
    float* bsm = (float*)(smc + OFF_BIAS);

    const int tid = threadIdx.x, l = tid & 31, w = tid >> 5;
    const int tq = l & 3;
    const int cta = blockIdx.x;
    const bool is0 = (cta < N0CTA);
    const int lc = is0 ? cta : (cta - N0CTA);

    // ---- stage weights into B-fragment smem layout (once) ----
    {
        const int nkp = is0 ? 256 : 512;    // k-pairs
        for (int i = tid; i < nkp * 32; i += NTHR) {
            int c = i & 31, kp = i >> 5, k = kp * 2;
            int gate = c & 3, ul = c >> 2;
            int grow = gate * HD + lc * 8 + ul;
            float w0, w1;
            if (is0)        { w0 = Whh0[(size_t)grow * HD + k];      w1 = Whh0[(size_t)grow * HD + k + 1]; }
            else if (k < HD){ w0 = Wih1[(size_t)grow * HD + k];      w1 = Wih1[(size_t)grow * HD + k + 1]; }
            else            { w0 = Whh1[(size_t)grow * HD + k - HD]; w1 = Whh1[(size_t)grow * HD + k - HD + 1]; }
            int C = k >> 4, C2 = C >> 1, Codd = C & 1;
            size_t off = ((size_t)(C2 * 4 + (c >> 3)) * 32 + 4 * (c & 7) + (kp & 3)) * 16
                       + (Codd * 2 + ((kp >> 2) & 1)) * 4;
            *(__nv_bfloat162*)(smc + off) =
                __nv_bfloat162(__float2bfloat16(w0), __float2bfloat16(w1));
        }
        if (!is0 && tid < 32) {
            int gate = tid & 3, ul = tid >> 2;
            int grow = gate * HD + lc * 8 + ul;
            bsm[tid] = bih1[grow] + bhh1[grow];
        }
    }
    __syncthreads();

    float cst[4] = {0.0f, 0.0f, 0.0f, 0.0f};

    if (is0) {
        // ================= layer 0 group =================
        for (int e = 0; e < TLEN; ++e) {
            const float* xp = g_xg + ((((size_t)e * N0CTA + cta) * 8 + w) * 4) * 128 + l * 4;
            float4 xv[4];
            #pragma unroll
            for (int f = 0; f < 4; ++f) xv[f] = __ldcs((const float4*)(xp + f * 128));

            const uint4* Ab = e ? g_h0f[(e - 1) & 7] : g_zf;
            float D[4][4];
            #pragma unroll
            for (int nf = 0; nf < 4; ++nf)
                #pragma unroll
                for (int q = 0; q < 4; ++q) D[nf][q] = 0.0f;

            uint4 aa[4][2];
            #pragma unroll
            for (int p = 0; p < 4; ++p) {
                aa[p][0] = __ldcg(&Ab[FIDX(w, 2 * p,     l)]);
                aa[p][1] = __ldcg(&Ab[FIDX(w, 2 * p + 1, l)]);
            }
            #pragma unroll
            for (int C2 = 0; C2 < 16; ++C2) {
                const int s = C2 & 3;
                uint4 a0 = aa[s][0], a1 = aa[s][1];
                if (C2 + 4 < 16) {
                    aa[s][0] = __ldcg(&Ab[FIDX(w, 2 * (C2 + 4),     l)]);
                    aa[s][1] = __ldcg(&Ab[FIDX(w, 2 * (C2 + 4) + 1, l)]);
                }
                #pragma unroll
                for (int nf = 0; nf < 4; ++nf) {
                    uint4 bq = Wf[(C2 * 4 + nf) * 32 + l];
                    mma16(D[nf], (const uint32_t*)&a0, bq.x, bq.y);
                    mma16(D[nf], (const uint32_t*)&a1, bq.z, bq.w);
                }
            }

            // ring back-pressure: h0[e & 7] overwrites h0[e-8]
            if (e >= 8) wait_ge(&g_gen1, (unsigned)(e - 7));

            #pragma unroll
            for (int nf = 0; nf < 4; ++nf)
                #pragma unroll
                for (int q = 0; q < 4; ++q) D[nf][q] += (&xv[nf].x)[q];

            epi8(D, cst, (char*)g_h0f[e & 7], cta * 8, w, l);
            group_sync(&g_cnt0, &g_gen0, N0CTA, (unsigned)(e + 1));
        }
    } else {
        // ================= layer 1 group (trails L0) =================
        for (int e = 1; e <= TLEN; ++e) {
            wait_ge(&g_gen0, (unsigned)e);          // h0[e-1] published
            const uint4* A0 = g_h0f[(e - 1) & 7];
            const uint4* A1 = (e >= 2) ? g_h1f[e & 1] : g_zf;

            float D[4][4];
            #pragma unroll
            for (int nf = 0; nf < 4; ++nf) {
                float b0 = bsm[nf * 8 + 2 * tq];
                float b1 = bsm[nf * 8 + 2 * tq + 1];
                D[nf][0] = b0; D[nf][1] = b1; D[nf][2] = b0; D[nf][3] = b1;
            }

            uint4 aa[4][2];
            #pragma unroll
            for (int p = 0; p < 4; ++p) {
                aa[p][0] = __ldcg(&A0[FIDX(w, 2 * p,     l)]);
                aa[p][1] = __ldcg(&A0[FIDX(w, 2 * p + 1, l)]);
            }
            #pragma unroll
            for (int C2 = 0; C2 < 32; ++C2) {
                const int s = C2 & 3;
                uint4 a0 = aa[s][0], a1 = aa[s][1];
                if (C2 + 4 < 32) {
                    const int cg = C2 + 4;
                    const uint4* S = (cg < 16) ? A0 : A1;
                    const int c = cg & 15;
                    aa[s][0] = __ldcg(&S[FIDX(w, 2 * c,     l)]);
                    aa[s][1] = __ldcg(&S[FIDX(w, 2 * c + 1, l)]);
                }
                #pragma unroll
                for (int nf = 0; nf < 4; ++nf) {
                    uint4 bq = Wf[(C2 * 4 + nf) * 32 + l];
                    mma16(D[nf], (const uint32_t*)&a0, bq.x, bq.y);
                    mma16(D[nf], (const uint32_t*)&a1, bq.z, bq.w);
                }
            }

            epi8(D, cst, (char*)g_h1f[(e - 1) & 1], lc * 8, w, l);
            group_sync(&g_cnt1, &g_gen1, N1CTA, (unsigned)e);
        }
    }

    // ---------------- FC head on CTA 0 ----------------
    if (cta == 0) {
        wait_ge(&g_gen1, (unsigned)TLEN);           // all of h1 published
        float* sw = (float*)smc;                    // reuse weight region
        for (int i = tid; i < HD * 32; i += NTHR) {
            int u = i >> 5, j = i & 31;
            sw[i] = fc1w[(size_t)j * HD + u];
        }
        __syncthreads();
        if (tid < BSZ) {
            const uint4* hb = g_h1f[(TLEN - 1) & 1];
            float s[32];
            #pragma unroll
            for (int j = 0; j < 32; ++j) s[j] = 0.0f;
            for (int u = 0; u < HD; ++u) {
                uint4 q = __ldcg(&hb[FIDX(tid >> 4, u >> 4, (tid & 7) * 4 + ((u & 7) >> 1))]);
                uint32_t rg = ((const uint32_t*)&q)[((tid >> 3) & 1) + 2 * ((u >> 3) & 1)];
                float v = __bfloat162float(((const __nv_bfloat16*)&rg)[u & 1]);
                const float4* ww = (const float4*)(sw + u * 32);
                #pragma unroll
                for (int j4 = 0; j4 < 8; ++j4) {
                    float4 wv = ww[j4];
                    s[4 * j4 + 0] += v * wv.x;
                    s[4 * j4 + 1] += v * wv.y;
                    s[4 * j4 + 2] += v * wv.z;
                    s[4 * j4 + 3] += v * wv.w;
                }
            }
            float y = fc2b[0];
            #pragma unroll
            for (int j = 0; j < 32; ++j) y += fc2w[j] * (s[j] + fc1b[j]);
            out[tid] = y;
        }
        __syncthreads();
    }

    // ---------------- finalize: reset counters for graph replay ----------------
    __syncthreads();
    __threadfence();
    if (tid == 0) {
        if (atomicAdd(&g_fin, 1u) == NALL - 1) {
            g_gen0 = 0;
            g_gen1 = 0;
            __threadfence();
            atomicExch(&g_fin, 0u);
        }
    }
}

// =====================================================================
extern "C" void kernel_launch(void* const* d_in, const int* in_sizes, int n_in,
                              void* d_out, int out_size)
{
    (void)in_sizes; (void)n_in; (void)out_size;
    const float* x    = (const float*)d_in[0];
    const float* Wih0 = (const float*)d_in[1];
    const float* Whh0 = (const float*)d_in[2];
    const float* bih0 = (const float*)d_in[3];
    const float* bhh0 = (const float*)d_in[4];
    const float* Wih1 = (const float*)d_in[5];
    const float* Whh1 = (const float*)d_in[6];
    const float* bih1 = (const float*)d_in[7];
    const float* bhh1 = (const float*)d_in[8];
    const float* fc1w = (const float*)d_in[9];
    const float* fc1b = (const float*)d_in[10];
    const float* fc2w = (const float*)d_in[11];
    const float* fc2b = (const float*)d_in[12];
    float* out = (float*)d_out;

    const int sm_x = 64 * XW_ST * 4 + 256;
    cudaFuncSetAttribute(xform0, cudaFuncAttributeMaxDynamicSharedMemorySize, sm_x);
    cudaFuncSetAttribute(rec,    cudaFuncAttributeMaxDynamicSharedMemorySize, SMEM_REC);

    xform0<<<dim3(N0CTA, TLEN / 8), NTHR, sm_x>>>(x, Wih0, bih0, bhh0);
    rec<<<NALL, NTHR, SMEM_REC>>>(Whh0, Wih1, Whh1, bih1, bhh1,
                                  fc1w, fc1b, fc2w, fc2b, out);
}

// round 10
// speedup vs baseline: 4.6770x; 1.0977x over previous
#include <cuda_runtime.h>
#include <cuda_bf16.h>
#include <cstdint>

#define TLEN 1024
#define BSZ  128
#define DIN  64
#define HD   512
#define N0CTA 64
#define N1CTA 64
#define NALL  128
#define NTHR  256

// fragment index: uint4 element for (16-row block R, 16-k block C, lane l)
#define FIDX(R, C, l) ((((R) * 32 + (C)) * 32) + (l))

// ---------------- device scratch (static, no allocations) ----------------
__device__ float g_xg[268435456];          // 1 GB: L0 xg frags [t][cta][w][nf][l][4]
__device__ uint4 g_h0f[8][8192];           // h0 bf16 A-frag ring (8 deep)
__device__ uint4 g_h1f[2][8192];           // h1 double buffer
__device__ uint4 g_zf[8192];               // stays zero
// each sync word on its own 256B line (separate LTS slices; no false sharing)
__device__ __align__(256) unsigned g_cnt0p[64];   // L0 arrivals (monotonic)
__device__ __align__(256) unsigned g_cnt1p[64];   // L1 arrivals (monotonic)
__device__ __align__(256) unsigned g_finp[64];    // finalize counter

// ---------------- helpers ----------------
__device__ __forceinline__ uint32_t tf32u(float x) {
    uint32_t u; asm("cvt.rna.tf32.f32 %0, %1;" : "=r"(u) : "f"(x)); return u;
}
__device__ __forceinline__ float tf32r(float x) { return __uint_as_float(tf32u(x)); }

__device__ __forceinline__ void mma8(float d[4], const uint32_t a[4], uint32_t b0, uint32_t b1) {
    asm volatile("mma.sync.aligned.m16n8k8.row.col.f32.tf32.tf32.f32 "
        "{%0,%1,%2,%3}, {%4,%5,%6,%7}, {%8,%9}, {%0,%1,%2,%3};"
        : "+f"(d[0]), "+f"(d[1]), "+f"(d[2]), "+f"(d[3])
        : "r"(a[0]), "r"(a[1]), "r"(a[2]), "r"(a[3]), "r"(b0), "r"(b1));
}
__device__ __forceinline__ void mma16(float d[4], const uint32_t* a, uint32_t b0, uint32_t b1) {
    asm volatile("mma.sync.aligned.m16n8k16.row.col.f32.bf16.bf16.f32 "
        "{%0,%1,%2,%3}, {%4,%5,%6,%7}, {%8,%9}, {%0,%1,%2,%3};"
        : "+f"(d[0]), "+f"(d[1]), "+f"(d[2]), "+f"(d[3])
        : "r"(a[0]), "r"(a[1]), "r"(a[2]), "r"(a[3]), "r"(b0), "r"(b1));
}

__device__ __forceinline__ float sigm(float x)  { return 1.0f / (1.0f + __expf(-x)); }
__device__ __forceinline__ float tanhp(float x) { return 2.0f / (1.0f + __expf(-2.0f * x)) - 1.0f; }

// release-arrive: orders all prior (syncthreads-covered) stores before the add
__device__ __forceinline__ void arrive(unsigned* c) {
    asm volatile("red.release.gpu.global.add.u32 [%0], 1;" :: "l"(c) : "memory");
}
// acquire-poll until counter >= tgt
__device__ __forceinline__ void poll_ge(unsigned* c, unsigned tgt) {
    unsigned v;
    do {
        asm volatile("ld.acquire.gpu.global.u32 %0, [%1];" : "=r"(v) : "l"(c) : "memory");
    } while (v < tgt);
}
// block-wide: arrive own counter and wait for whole group (tid0 polls)
__device__ __forceinline__ void group_barrier(unsigned* c, unsigned tgt) {
    __syncthreads();
    if (threadIdx.x == 0) { arrive(c); poll_ge(c, tgt); }
    __syncthreads();
}
// block-wide: wait for other group's counter
__device__ __forceinline__ void group_wait(unsigned* c, unsigned tgt) {
    if (threadIdx.x == 0) poll_ge(c, tgt);
    __syncthreads();
}

// LSTM epilogue, 8x1 tiling (unchanged from R9)
__device__ __forceinline__ void epi8(float D[4][4], float* cst, char* hbuf,
                                     int ubase, int w, int l) {
    const int gr = l >> 2, tq = l & 3;
    const bool odd = tq & 1;
    #pragma unroll
    for (int nf = 0; nf < 4; ++nf) {
        float d0 = D[nf][0], d1 = D[nf][1], d2 = D[nf][2], d3 = D[nf][3];
        float p0 = __shfl_xor_sync(0xffffffffu, d0, 1);
        float p1 = __shfl_xor_sync(0xffffffffu, d1, 1);
        float p2 = __shfl_xor_sync(0xffffffffu, d2, 1);
        float p3 = __shfl_xor_sync(0xffffffffu, d3, 1);
        float gi = odd ? p2 : d0;
        float gf = odd ? p3 : d1;
        float gg = odd ? d2 : p0;
        float go = odd ? d3 : p1;
        float c = sigm(gf) * cst[nf] + sigm(gi) * tanhp(gg);
        cst[nf] = c;
        float h = sigm(go) * tanhp(c);
        float hp = __shfl_xor_sync(0xffffffffu, h, 2);
        if (!(tq & 2)) {                       // owns even unit; partner has u+1
            int u = ubase + nf * 2;
            __nv_bfloat162 pk(__float2bfloat16(h), __float2bfloat16(hp));
            size_t off = (size_t)(((w * 32 + (u >> 4)) * 32) + gr * 4 + nf) * 16
                       + ((odd ? 1 : 0) + 2 * ((u >> 3) & 1)) * 4;
            *(uint32_t*)(hbuf + off) = *(uint32_t*)&pk;
        }
    }
}

// =====================================================================
// xform0: g_xg = bias + x @ Wih0^T in per-thread D-fragment layout (8x1 tiling).
// =====================================================================
#define XW_ST 36
__global__ void __launch_bounds__(NTHR, 1)
xform0(const float* __restrict__ x, const float* __restrict__ Wih,
       const float* __restrict__ bih, const float* __restrict__ bhh)
{
    extern __shared__ float sm[];
    float* Ws = sm;                  // [64][XW_ST]
    float* bs = sm + 64 * XW_ST;

    const int tid = threadIdx.x, l = tid & 31, w = tid >> 5;
    const int gr = l >> 2, tq = l & 3;
    const int cta = blockIdx.x;

    for (int i = tid; i < 64 * 32; i += NTHR) {
        int k = i >> 5, c = i & 31;
        int gate = c & 3, ul = c >> 2;
        int grow = gate * HD + cta * 8 + ul;
        Ws[k * XW_ST + c] = tf32r(Wih[(size_t)grow * DIN + k]);
    }
    if (tid < 32) {
        int gate = tid & 3, ul = tid >> 2;
        int grow = gate * HD + cta * 8 + ul;
        bs[tid] = bih[grow] + bhh[grow];
    }
    __syncthreads();

    const int r0 = 16 * w + gr;
    for (int tt = 0; tt < 8; ++tt) {
        const int t = blockIdx.y * 8 + tt;
        float D[4][4];
        #pragma unroll
        for (int nf = 0; nf < 4; ++nf) {
            float b0 = bs[nf * 8 + 2 * tq];
            float b1 = bs[nf * 8 + 2 * tq + 1];
            D[nf][0] = b0; D[nf][1] = b1; D[nf][2] = b0; D[nf][3] = b1;
        }
        #pragma unroll
        for (int kk = 0; kk < 8; ++kk) {
            const int ko = kk * 8;
            const float* xp  = x + (size_t)r0 * (TLEN * DIN) + (size_t)t * DIN + ko + tq;
            const float* xp8 = xp + (size_t)8 * (TLEN * DIN);
            uint32_t a[4] = { tf32u(xp[0]), tf32u(xp8[0]), tf32u(xp[4]), tf32u(xp8[4]) };
            #pragma unroll
            for (int nf = 0; nf < 4; ++nf) {
                uint32_t b0 = __float_as_uint(Ws[(ko + tq) * XW_ST + nf * 8 + gr]);
                uint32_t b1 = __float_as_uint(Ws[(ko + tq + 4) * XW_ST + nf * 8 + gr]);
                mma8(D[nf], a, b0, b1);
            }
        }
        float* dst = g_xg + ((((size_t)t * N0CTA + cta) * 8 + w) * 4) * 128 + l * 4;
        #pragma unroll
        for (int nf = 0; nf < 4; ++nf)
            *(float4*)(dst + nf * 128) = make_float4(D[nf][0], D[nf][1], D[nf][2], D[nf][3]);
    }
}

// =====================================================================
// rec: 128 persistent CTAs, two decoupled groups.
//   CTA 0..63   : layer0, 32 cols, K=512 (h0[t-1]), xg added in epilogue
//   CTA 64..127 : layer1, 32 cols, K=1024 = [h1(t-1); h0(t)] — own half first
// Sync: per-group monotonic counters, release-RED arrive + acquire-LD poll.
// =====================================================================
#define OFF_BIAS 65536
#define SMEM_REC (OFF_BIAS + 512)

__global__ void __launch_bounds__(NTHR, 1)
rec(const float* __restrict__ Whh0,
    const float* __restrict__ Wih1, const float* __restrict__ Whh1,
    const float* __restrict__ bih1, const float* __restrict__ bhh1,
    const float* __restrict__ fc1w, const float* __restrict__ fc1b,
    const float* __restrict__ fc2w, const float* __restrict__ fc2b,
    float* __restrict__ out)
{
    extern __shared__ char smc[];
    uint4* Wf = (uint4*)smc;
    float* bsm = (float*)(smc + OFF_BIAS);

    const int tid = threadIdx.x, l = tid & 31, w = tid >> 5;
    const int tq = l & 3;
    const int cta = blockIdx.x;
    const bool is0 = (cta < N0CTA);
    const int lc = is0 ? cta : (cta - N0CTA);

    // ---- stage weights into B-fragment smem layout (once) ----
    {
        const int nkp = is0 ? 256 : 512;    // k-pairs
        for (int i = tid; i < nkp * 32; i += NTHR) {
            int c = i & 31, kp = i >> 5, k = kp * 2;
            int gate = c & 3, ul = c >> 2;
            int grow = gate * HD + lc * 8 + ul;
            float w0, w1;
            if (is0)        { w0 = Whh0[(size_t)grow * HD + k];      w1 = Whh0[(size_t)grow * HD + k + 1]; }
            else if (k < HD){ w0 = Wih1[(size_t)grow * HD + k];      w1 = Wih1[(size_t)grow * HD + k + 1]; }
            else            { w0 = Whh1[(size_t)grow * HD + k - HD]; w1 = Whh1[(size_t)grow * HD + k - HD + 1]; }
            int C = k >> 4, C2 = C >> 1, Codd = C & 1;
            size_t off = ((size_t)(C2 * 4 + (c >> 3)) * 32 + 4 * (c & 7) + (kp & 3)) * 16
                       + (Codd * 2 + ((kp >> 2) & 1)) * 4;
            *(__nv_bfloat162*)(smc + off) =
                __nv_bfloat162(__float2bfloat16(w0), __float2bfloat16(w1));
        }
        if (!is0 && tid < 32) {
            int gate = tid & 3, ul = tid >> 2;
            int grow = gate * HD + lc * 8 + ul;
            bsm[tid] = bih1[grow] + bhh1[grow];
        }
    }
    __syncthreads();

    float cst[4] = {0.0f, 0.0f, 0.0f, 0.0f};

    if (is0) {
        // ================= layer 0 group =================
        for (int e = 0; e < TLEN; ++e) {
            const float* xp = g_xg + ((((size_t)e * N0CTA + cta) * 8 + w) * 4) * 128 + l * 4;
            float4 xv[4];
            #pragma unroll
            for (int f = 0; f < 4; ++f) xv[f] = __ldcs((const float4*)(xp + f * 128));

            const uint4* Ab = e ? g_h0f[(e - 1) & 7] : g_zf;
            float D[4][4];
            #pragma unroll
            for (int nf = 0; nf < 4; ++nf)
                #pragma unroll
                for (int q = 0; q < 4; ++q) D[nf][q] = 0.0f;

            uint4 aa[4][2];
            #pragma unroll
            for (int p = 0; p < 4; ++p) {
                aa[p][0] = __ldcg(&Ab[FIDX(w, 2 * p,     l)]);
                aa[p][1] = __ldcg(&Ab[FIDX(w, 2 * p + 1, l)]);
            }
            #pragma unroll
            for (int C2 = 0; C2 < 16; ++C2) {
                const int s = C2 & 3;
                uint4 a0 = aa[s][0], a1 = aa[s][1];
                if (C2 + 4 < 16) {
                    aa[s][0] = __ldcg(&Ab[FIDX(w, 2 * (C2 + 4),     l)]);
                    aa[s][1] = __ldcg(&Ab[FIDX(w, 2 * (C2 + 4) + 1, l)]);
                }
                #pragma unroll
                for (int nf = 0; nf < 4; ++nf) {
                    uint4 bq = Wf[(C2 * 4 + nf) * 32 + l];
                    mma16(D[nf], (const uint32_t*)&a0, bq.x, bq.y);
                    mma16(D[nf], (const uint32_t*)&a1, bq.z, bq.w);
                }
            }

            // ring back-pressure: before overwriting h0[e & 7], L1 must be past e-7
            if (e >= 8) group_wait(g_cnt1p, 64u * (unsigned)(e - 7));

            #pragma unroll
            for (int nf = 0; nf < 4; ++nf)
                #pragma unroll
                for (int q = 0; q < 4; ++q) D[nf][q] += (&xv[nf].x)[q];

            epi8(D, cst, (char*)g_h0f[e & 7], cta * 8, w, l);
            group_barrier(g_cnt0p, 64u * (unsigned)(e + 1));
        }
    } else {
        // ================= layer 1 group (trails L0) =================
        for (int e = 1; e <= TLEN; ++e) {
            const uint4* A1 = (e >= 2) ? g_h1f[e & 1] : g_zf;   // h1[t-1], own data

            float D[4][4];
            #pragma unroll
            for (int nf = 0; nf < 4; ++nf) {
                float b0 = bsm[nf * 8 + 2 * tq];
                float b1 = bsm[nf * 8 + 2 * tq + 1];
                D[nf][0] = b0; D[nf][1] = b1; D[nf][2] = b0; D[nf][3] = b1;
            }

            // ---- own half first (k 512..1023): no external wait needed ----
            uint4 aa[4][2];
            #pragma unroll
            for (int p = 0; p < 4; ++p) {
                aa[p][0] = __ldcg(&A1[FIDX(w, 2 * p,     l)]);
                aa[p][1] = __ldcg(&A1[FIDX(w, 2 * p + 1, l)]);
            }
            #pragma unroll
            for (int C2 = 0; C2 < 16; ++C2) {
                const int s = C2 & 3;
                uint4 a0 = aa[s][0], a1 = aa[s][1];
                if (C2 + 4 < 16) {
                    aa[s][0] = __ldcg(&A1[FIDX(w, 2 * (C2 + 4),     l)]);
                    aa[s][1] = __ldcg(&A1[FIDX(w, 2 * (C2 + 4) + 1, l)]);
                }
                #pragma unroll
                for (int nf = 0; nf < 4; ++nf) {
                    uint4 bq = Wf[((C2 + 16) * 4 + nf) * 32 + l];
                    mma16(D[nf], (const uint32_t*)&a0, bq.x, bq.y);
                    mma16(D[nf], (const uint32_t*)&a1, bq.z, bq.w);
                }
            }

            // ---- wait for h0[e-1], then h0 half (k 0..511) ----
            group_wait(g_cnt0p, 64u * (unsigned)e);
            const uint4* A0 = g_h0f[(e - 1) & 7];
            #pragma unroll
            for (int p = 0; p < 4; ++p) {
                aa[p][0] = __ldcg(&A0[FIDX(w, 2 * p,     l)]);
                aa[p][1] = __ldcg(&A0[FIDX(w, 2 * p + 1, l)]);
            }
            #pragma unroll
            for (int C2 = 0; C2 < 16; ++C2) {
                const int s = C2 & 3;
                uint4 a0 = aa[s][0], a1 = aa[s][1];
                if (C2 + 4 < 16) {
                    aa[s][0] = __ldcg(&A0[FIDX(w, 2 * (C2 + 4),     l)]);
                    aa[s][1] = __ldcg(&A0[FIDX(w, 2 * (C2 + 4) + 1, l)]);
                }
                #pragma unroll
                for (int nf = 0; nf < 4; ++nf) {
                    uint4 bq = Wf[(C2 * 4 + nf) * 32 + l];
                    mma16(D[nf], (const uint32_t*)&a0, bq.x, bq.y);
                    mma16(D[nf], (const uint32_t*)&a1, bq.z, bq.w);
                }
            }

            epi8(D, cst, (char*)g_h1f[(e - 1) & 1], lc * 8, w, l);
            group_barrier(g_cnt1p, 64u * (unsigned)e);
        }
    }

    // ---------------- FC head on CTA 0 ----------------
    if (cta == 0) {
        group_wait(g_cnt1p, 64u * (unsigned)TLEN);   // all of h1 published
        float* sw = (float*)smc;                     // reuse weight region
        for (int i = tid; i < HD * 32; i += NTHR) {
            int u = i >> 5, j = i & 31;
            sw[i] = fc1w[(size_t)j * HD + u];
        }
        __syncthreads();
        if (tid < BSZ) {
            const uint4* hb = g_h1f[(TLEN - 1) & 1];
            float s[32];
            #pragma unroll
            for (int j = 0; j < 32; ++j) s[j] = 0.0f;
            for (int u = 0; u < HD; ++u) {
                uint4 q = __ldcg(&hb[FIDX(tid >> 4, u >> 4, (tid & 7) * 4 + ((u & 7) >> 1))]);
                uint32_t rg = ((const uint32_t*)&q)[((tid >> 3) & 1) + 2 * ((u >> 3) & 1)];
                float v = __bfloat162float(((const __nv_bfloat16*)&rg)[u & 1]);
                const float4* ww = (const float4*)(sw + u * 32);
                #pragma unroll
                for (int j4 = 0; j4 < 8; ++j4) {
                    float4 wv = ww[j4];
                    s[4 * j4 + 0] += v * wv.x;
                    s[4 * j4 + 1] += v * wv.y;
                    s[4 * j4 + 2] += v * wv.z;
                    s[4 * j4 + 3] += v * wv.w;
                }
            }
            float y = fc2b[0];
            #pragma unroll
            for (int j = 0; j < 32; ++j) y += fc2w[j] * (s[j] + fc1b[j]);
            out[tid] = y;
        }
        __syncthreads();
    }

    // ---------------- finalize: reset counters for graph replay ----------------
    __syncthreads();
    __threadfence();
    if (tid == 0) {
        if (atomicAdd(&g_finp[0], 1u) == NALL - 1) {
            g_cnt0p[0] = 0;
            g_cnt1p[0] = 0;
            __threadfence();
            atomicExch(&g_finp[0], 0u);
        }
    }
}

// =====================================================================
extern "C" void kernel_launch(void* const* d_in, const int* in_sizes, int n_in,
                              void* d_out, int out_size)
{
    (void)in_sizes; (void)n_in; (void)out_size;
    const float* x    = (const float*)d_in[0];
    const float* Wih0 = (const float*)d_in[1];
    const float* Whh0 = (const float*)d_in[2];
    const float* bih0 = (const float*)d_in[3];
    const float* bhh0 = (const float*)d_in[4];
    const float* Wih1 = (const float*)d_in[5];
    const float* Whh1 = (const float*)d_in[6];
    const float* bih1 = (const float*)d_in[7];
    const float* bhh1 = (const float*)d_in[8];
    const float* fc1w = (const float*)d_in[9];
    const float* fc1b = (const float*)d_in[10];
    const float* fc2w = (const float*)d_in[11];
    const float* fc2b = (const float*)d_in[12];
    float* out = (float*)d_out;

    const int sm_x = 64 * XW_ST * 4 + 256;
    cudaFuncSetAttribute(xform0, cudaFuncAttributeMaxDynamicSharedMemorySize, sm_x);
    cudaFuncSetAttribute(rec,    cudaFuncAttributeMaxDynamicSharedMemorySize, SMEM_REC);

    xform0<<<dim3(N0CTA, TLEN / 8), NTHR, sm_x>>>(x, Wih0, bih0, bhh0);
    rec<<<NALL, NTHR, SMEM_REC>>>(Whh0, Wih1, Whh1, bih1, bhh1,
                                  fc1w, fc1b, fc2w, fc2b, out);
}

// round 11
// speedup vs baseline: 5.1003x; 1.0905x over previous
#include <cuda_runtime.h>
#include <cuda_bf16.h>
#include <cstdint>

#define TLEN 1024
#define BSZ  128
#define DIN  64
#define HD   512
#define N0CTA 64
#define N1CTA 64
#define NALL  128
#define NTHR  256

// fragment index: uint4 element for (16-row block R, 16-k block C, lane l)
#define FIDX(R, C, l) ((((R) * 32 + (C)) * 32) + (l))

// ---------------- device scratch (static, no allocations) ----------------
__device__ float g_xg[268435456];          // 1 GB: L0 xg frags [t][cta][mf][nf][l][4]
__device__ uint4 g_h0f[8][8192];           // h0 bf16 A-frag ring (8 deep)
__device__ uint4 g_h1f[2][8192];           // h1 double buffer
__device__ uint4 g_zf[8192];               // stays zero
// each sync word on its own 256B line
__device__ __align__(256) unsigned g_cnt0p[64];   // L0 arrivals (monotonic)
__device__ __align__(256) unsigned g_cnt1p[64];   // L1 arrivals (monotonic)
__device__ __align__(256) unsigned g_finp[64];    // finalize counter

// ---------------- helpers ----------------
__device__ __forceinline__ uint32_t tf32u(float x) {
    uint32_t u; asm("cvt.rna.tf32.f32 %0, %1;" : "=r"(u) : "f"(x)); return u;
}
__device__ __forceinline__ float tf32r(float x) { return __uint_as_float(tf32u(x)); }

__device__ __forceinline__ void mma8(float d[4], const uint32_t a[4], uint32_t b0, uint32_t b1) {
    asm volatile("mma.sync.aligned.m16n8k8.row.col.f32.tf32.tf32.f32 "
        "{%0,%1,%2,%3}, {%4,%5,%6,%7}, {%8,%9}, {%0,%1,%2,%3};"
        : "+f"(d[0]), "+f"(d[1]), "+f"(d[2]), "+f"(d[3])
        : "r"(a[0]), "r"(a[1]), "r"(a[2]), "r"(a[3]), "r"(b0), "r"(b1));
}
__device__ __forceinline__ void mma16(float d[4], const uint32_t* a, uint32_t b0, uint32_t b1) {
    asm volatile("mma.sync.aligned.m16n8k16.row.col.f32.bf16.bf16.f32 "
        "{%0,%1,%2,%3}, {%4,%5,%6,%7}, {%8,%9}, {%0,%1,%2,%3};"
        : "+f"(d[0]), "+f"(d[1]), "+f"(d[2]), "+f"(d[3])
        : "r"(a[0]), "r"(a[1]), "r"(a[2]), "r"(a[3]), "r"(b0), "r"(b1));
}

__device__ __forceinline__ float sigm(float x)  { return 1.0f / (1.0f + __expf(-x)); }
__device__ __forceinline__ float tanhp(float x) { return 2.0f / (1.0f + __expf(-2.0f * x)) - 1.0f; }

// release-arrive / acquire-poll on monotonic counters
__device__ __forceinline__ void arrive(unsigned* c) {
    asm volatile("red.release.gpu.global.add.u32 [%0], 1;" :: "l"(c) : "memory");
}
__device__ __forceinline__ void poll_ge(unsigned* c, unsigned tgt) {
    unsigned v;
    do {
        asm volatile("ld.acquire.gpu.global.u32 %0, [%1];" : "=r"(v) : "l"(c) : "memory");
    } while (v < tgt);
}
__device__ __forceinline__ void group_barrier(unsigned* c, unsigned tgt) {
    __syncthreads();
    if (threadIdx.x == 0) { arrive(c); poll_ge(c, tgt); }
    __syncthreads();
}
// warp-scope wait (lane 0 polls; leader-acquire + syncwarp publishes to warp)
__device__ __forceinline__ void warp_wait(unsigned* c, unsigned tgt) {
    if ((threadIdx.x & 31) == 0) poll_ge(c, tgt);
    __syncwarp();
}

// LSTM epilogue on one row-block (R), 4 nf frags
__device__ __forceinline__ void epi4(float D[4][4], float* cst, char* hbuf,
                                     int ubase, int R, int l) {
    const int gr = l >> 2, tq = l & 3;
    const bool odd = tq & 1;
    #pragma unroll
    for (int nf = 0; nf < 4; ++nf) {
        float d0 = D[nf][0], d1 = D[nf][1], d2 = D[nf][2], d3 = D[nf][3];
        float p0 = __shfl_xor_sync(0xffffffffu, d0, 1);
        float p1 = __shfl_xor_sync(0xffffffffu, d1, 1);
        float p2 = __shfl_xor_sync(0xffffffffu, d2, 1);
        float p3 = __shfl_xor_sync(0xffffffffu, d3, 1);
        float gi = odd ? p2 : d0;
        float gf = odd ? p3 : d1;
        float gg = odd ? d2 : p0;
        float go = odd ? d3 : p1;
        float c = sigm(gf) * cst[nf] + sigm(gi) * tanhp(gg);
        cst[nf] = c;
        float h = sigm(go) * tanhp(c);
        float hp = __shfl_xor_sync(0xffffffffu, h, 2);
        if (!(tq & 2)) {                       // owns even unit; partner has u+1
            int u = ubase + nf * 2;
            int nfc = (u & 15) >> 1;
            __nv_bfloat162 pk(__float2bfloat16(h), __float2bfloat16(hp));
            size_t off = (size_t)(((R * 32 + (u >> 4)) * 32) + gr * 4 + (nfc & 3)) * 16
                       + ((odd ? 1 : 0) + 2 * (nfc >> 2)) * 4;
            *(uint32_t*)(hbuf + off) = *(uint32_t*)&pk;
        }
    }
}

// =====================================================================
// xform0: g_xg = bias + x @ Wih0^T in per-thread D-fragment layout.
// (unchanged from R10 — w coincides with row-block mf)
// =====================================================================
#define XW_ST 36
__global__ void __launch_bounds__(NTHR, 1)
xform0(const float* __restrict__ x, const float* __restrict__ Wih,
       const float* __restrict__ bih, const float* __restrict__ bhh)
{
    extern __shared__ float sm[];
    float* Ws = sm;                  // [64][XW_ST]
    float* bs = sm + 64 * XW_ST;

    const int tid = threadIdx.x, l = tid & 31, w = tid >> 5;
    const int gr = l >> 2, tq = l & 3;
    const int cta = blockIdx.x;

    for (int i = tid; i < 64 * 32; i += NTHR) {
        int k = i >> 5, c = i & 31;
        int gate = c & 3, ul = c >> 2;
        int grow = gate * HD + cta * 8 + ul;
        Ws[k * XW_ST + c] = tf32r(Wih[(size_t)grow * DIN + k]);
    }
    if (tid < 32) {
        int gate = tid & 3, ul = tid >> 2;
        int grow = gate * HD + cta * 8 + ul;
        bs[tid] = bih[grow] + bhh[grow];
    }
    __syncthreads();

    const int r0 = 16 * w + gr;
    for (int tt = 0; tt < 8; ++tt) {
        const int t = blockIdx.y * 8 + tt;
        float D[4][4];
        #pragma unroll
        for (int nf = 0; nf < 4; ++nf) {
            float b0 = bs[nf * 8 + 2 * tq];
            float b1 = bs[nf * 8 + 2 * tq + 1];
            D[nf][0] = b0; D[nf][1] = b1; D[nf][2] = b0; D[nf][3] = b1;
        }
        #pragma unroll
        for (int kk = 0; kk < 8; ++kk) {
            const int ko = kk * 8;
            const float* xp  = x + (size_t)r0 * (TLEN * DIN) + (size_t)t * DIN + ko + tq;
            const float* xp8 = xp + (size_t)8 * (TLEN * DIN);
            uint32_t a[4] = { tf32u(xp[0]), tf32u(xp8[0]), tf32u(xp[4]), tf32u(xp8[4]) };
            #pragma unroll
            for (int nf = 0; nf < 4; ++nf) {
                uint32_t b0 = __float_as_uint(Ws[(ko + tq) * XW_ST + nf * 8 + gr]);
                uint32_t b1 = __float_as_uint(Ws[(ko + tq + 4) * XW_ST + nf * 8 + gr]);
                mma8(D[nf], a, b0, b1);
            }
        }
        float* dst = g_xg + ((((size_t)t * N0CTA + cta) * 8 + w) * 4) * 128 + l * 4;
        #pragma unroll
        for (int nf = 0; nf < 4; ++nf)
            *(float4*)(dst + nf * 128) = make_float4(D[nf][0], D[nf][1], D[nf][2], D[nf][3]);
    }
}

// =====================================================================
// rec: 128 persistent CTAs, two decoupled groups, K-split warp pairs.
//   Warp (wq = w&3, kh = w>>2): partial sums over K-half kh for
//   row-blocks {2wq, 2wq+1}, 4 nf frags; finalizes row-block 2wq+kh
//   after a smem exchange+reduction with partner warp w^4.
//   L1: kh=1 <-> h1-half (no wait), kh=0 <-> h0-half (warp-scope wait).
// =====================================================================
#define OFF_BIAS 65536
#define OFF_XCH  66048
#define SMEM_REC (OFF_XCH + 16384)

__global__ void __launch_bounds__(NTHR, 1)
rec(const float* __restrict__ Whh0,
    const float* __restrict__ Wih1, const float* __restrict__ Whh1,
    const float* __restrict__ bih1, const float* __restrict__ bhh1,
    const float* __restrict__ fc1w, const float* __restrict__ fc1b,
    const float* __restrict__ fc2w, const float* __restrict__ fc2b,
    float* __restrict__ out)
{
    extern __shared__ char smc[];
    uint4* Wf  = (uint4*)smc;
    float* bsm = (float*)(smc + OFF_BIAS);
    float4* xch = (float4*)(smc + OFF_XCH);    // [w][j 0..3][lane]

    const int tid = threadIdx.x, l = tid & 31, w = tid >> 5;
    const int tq = l & 3;
    const int wq = w & 3, kh = w >> 2;
    const int mfA = 2 * wq, mfB = 2 * wq + 1;
    const int fin = 2 * wq + kh;               // row-block this warp finalizes
    const int cta = blockIdx.x;
    const bool is0 = (cta < N0CTA);
    const int lc = is0 ? cta : (cta - N0CTA);

    // ---- stage weights into B-fragment smem layout (once) ----
    {
        const int nkp = is0 ? 256 : 512;    // k-pairs
        for (int i = tid; i < nkp * 32; i += NTHR) {
            int c = i & 31, kp = i >> 5, k = kp * 2;
            int gate = c & 3, ul = c >> 2;
            int grow = gate * HD + lc * 8 + ul;
            float w0, w1;
            if (is0)        { w0 = Whh0[(size_t)grow * HD + k];      w1 = Whh0[(size_t)grow * HD + k + 1]; }
            else if (k < HD){ w0 = Wih1[(size_t)grow * HD + k];      w1 = Wih1[(size_t)grow * HD + k + 1]; }
            else            { w0 = Whh1[(size_t)grow * HD + k - HD]; w1 = Whh1[(size_t)grow * HD + k - HD + 1]; }
            int C = k >> 4, C2 = C >> 1, Codd = C & 1;
            size_t off = ((size_t)(C2 * 4 + (c >> 3)) * 32 + 4 * (c & 7) + (kp & 3)) * 16
                       + (Codd * 2 + ((kp >> 2) & 1)) * 4;
            *(__nv_bfloat162*)(smc + off) =
                __nv_bfloat162(__float2bfloat16(w0), __float2bfloat16(w1));
        }
        if (!is0 && tid < 32) {
            int gate = tid & 3, ul = tid >> 2;
            int grow = gate * HD + lc * 8 + ul;
            bsm[tid] = bih1[grow] + bhh1[grow];
        }
    }
    __syncthreads();

    float cst[4] = {0.0f, 0.0f, 0.0f, 0.0f};

    if (is0) {
        // ================= layer 0 group =================
        for (int e = 0; e < TLEN; ++e) {
            // xg frags for the row-block we finalize (streaming)
            const float* xp = g_xg + ((((size_t)e * N0CTA + cta) * 8 + fin) * 4) * 128 + l * 4;
            float4 xv[4];
            #pragma unroll
            for (int f = 0; f < 4; ++f) xv[f] = __ldcs((const float4*)(xp + f * 128));

            const uint4* Ab = e ? g_h0f[(e - 1) & 7] : g_zf;
            float P[2][4][4];
            #pragma unroll
            for (int m = 0; m < 2; ++m)
                #pragma unroll
                for (int nf = 0; nf < 4; ++nf)
                    #pragma unroll
                    for (int q = 0; q < 4; ++q) P[m][nf][q] = 0.0f;

            // K-half kh: weight C2 = kh*8 + 0..7, A C-chunks = kh*16 + ...
            uint4 aa[2][4];
            {
                const int C = kh * 16;
                aa[0][0] = __ldcg(&Ab[FIDX(mfA, C,     l)]);
                aa[0][1] = __ldcg(&Ab[FIDX(mfA, C + 1, l)]);
                aa[0][2] = __ldcg(&Ab[FIDX(mfB, C,     l)]);
                aa[0][3] = __ldcg(&Ab[FIDX(mfB, C + 1, l)]);
            }
            #pragma unroll
            for (int i = 0; i < 8; ++i) {
                const int cur = i & 1, nxt = cur ^ 1;
                if (i < 7) {
                    const int C = kh * 16 + 2 * (i + 1);
                    aa[nxt][0] = __ldcg(&Ab[FIDX(mfA, C,     l)]);
                    aa[nxt][1] = __ldcg(&Ab[FIDX(mfA, C + 1, l)]);
                    aa[nxt][2] = __ldcg(&Ab[FIDX(mfB, C,     l)]);
                    aa[nxt][3] = __ldcg(&Ab[FIDX(mfB, C + 1, l)]);
                }
                const int C2 = kh * 8 + i;
                #pragma unroll
                for (int nf = 0; nf < 4; ++nf) {
                    uint4 bq = Wf[(C2 * 4 + nf) * 32 + l];
                    mma16(P[0][nf], (const uint32_t*)&aa[cur][0], bq.x, bq.y);
                    mma16(P[0][nf], (const uint32_t*)&aa[cur][1], bq.z, bq.w);
                    mma16(P[1][nf], (const uint32_t*)&aa[cur][2], bq.x, bq.y);
                    mma16(P[1][nf], (const uint32_t*)&aa[cur][3], bq.z, bq.w);
                }
            }

            // exchange: store partner's row-block partial (index 1-kh)
            #pragma unroll
            for (int nf = 0; nf < 4; ++nf)
                xch[(w * 4 + nf) * 32 + l] = make_float4(P[1 - kh][nf][0], P[1 - kh][nf][1],
                                                          P[1 - kh][nf][2], P[1 - kh][nf][3]);
            // ring back-pressure (fast path) folded into the reduction sync
            if (tid == 0 && e >= 8) poll_ge(g_cnt1p, 64u * (unsigned)(e - 7));
            __syncthreads();

            float D[4][4];
            #pragma unroll
            for (int nf = 0; nf < 4; ++nf) {
                float4 q = xch[((w ^ 4) * 4 + nf) * 32 + l];
                D[nf][0] = P[kh][nf][0] + q.x + (&xv[nf].x)[0];
                D[nf][1] = P[kh][nf][1] + q.y + (&xv[nf].x)[1];
                D[nf][2] = P[kh][nf][2] + q.z + (&xv[nf].x)[2];
                D[nf][3] = P[kh][nf][3] + q.w + (&xv[nf].x)[3];
            }
            epi4(D, cst, (char*)g_h0f[e & 7], cta * 8, fin, l);
            group_barrier(g_cnt0p, 64u * (unsigned)(e + 1));
        }
    } else {
        // ================= layer 1 group (trails L0) =================
        for (int e = 1; e <= TLEN; ++e) {
            const uint4* Ab;
            int C2base;
            if (kh == 1) {                       // own h1 half — no external wait
                Ab = (e >= 2) ? g_h1f[e & 1] : g_zf;
                C2base = 16;
            } else {                             // h0 half — warp-scope wait
                warp_wait(g_cnt0p, 64u * (unsigned)e);
                Ab = g_h0f[(e - 1) & 7];
                C2base = 0;
            }

            float P[2][4][4];
            #pragma unroll
            for (int m = 0; m < 2; ++m)
                #pragma unroll
                for (int nf = 0; nf < 4; ++nf)
                    #pragma unroll
                    for (int q = 0; q < 4; ++q) P[m][nf][q] = 0.0f;

            uint4 aa[2][4];
            aa[0][0] = __ldcg(&Ab[FIDX(mfA, 0, l)]);
            aa[0][1] = __ldcg(&Ab[FIDX(mfA, 1, l)]);
            aa[0][2] = __ldcg(&Ab[FIDX(mfB, 0, l)]);
            aa[0][3] = __ldcg(&Ab[FIDX(mfB, 1, l)]);
            #pragma unroll
            for (int i = 0; i < 16; ++i) {
                const int cur = i & 1, nxt = cur ^ 1;
                if (i < 15) {
                    const int C = 2 * (i + 1);
                    aa[nxt][0] = __ldcg(&Ab[FIDX(mfA, C,     l)]);
                    aa[nxt][1] = __ldcg(&Ab[FIDX(mfA, C + 1, l)]);
                    aa[nxt][2] = __ldcg(&Ab[FIDX(mfB, C,     l)]);
                    aa[nxt][3] = __ldcg(&Ab[FIDX(mfB, C + 1, l)]);
                }
                const int C2 = C2base + i;
                #pragma unroll
                for (int nf = 0; nf < 4; ++nf) {
                    uint4 bq = Wf[(C2 * 4 + nf) * 32 + l];
                    mma16(P[0][nf], (const uint32_t*)&aa[cur][0], bq.x, bq.y);
                    mma16(P[0][nf], (const uint32_t*)&aa[cur][1], bq.z, bq.w);
                    mma16(P[1][nf], (const uint32_t*)&aa[cur][2], bq.x, bq.y);
                    mma16(P[1][nf], (const uint32_t*)&aa[cur][3], bq.z, bq.w);
                }
            }

            #pragma unroll
            for (int nf = 0; nf < 4; ++nf)
                xch[(w * 4 + nf) * 32 + l] = make_float4(P[1 - kh][nf][0], P[1 - kh][nf][1],
                                                          P[1 - kh][nf][2], P[1 - kh][nf][3]);
            __syncthreads();

            float D[4][4];
            #pragma unroll
            for (int nf = 0; nf < 4; ++nf) {
                float4 q = xch[((w ^ 4) * 4 + nf) * 32 + l];
                float b0 = bsm[nf * 8 + 2 * tq];
                float b1 = bsm[nf * 8 + 2 * tq + 1];
                D[nf][0] = P[kh][nf][0] + q.x + b0;
                D[nf][1] = P[kh][nf][1] + q.y + b1;
                D[nf][2] = P[kh][nf][2] + q.z + b0;
                D[nf][3] = P[kh][nf][3] + q.w + b1;
            }
            epi4(D, cst, (char*)g_h1f[(e - 1) & 1], lc * 8, fin, l);
            group_barrier(g_cnt1p, 64u * (unsigned)e);
        }
    }

    // ---------------- FC head on CTA 0 ----------------
    if (cta == 0) {
        if (tid == 0) poll_ge(g_cnt1p, 64u * (unsigned)TLEN);
        __syncthreads();
        float* sw = (float*)smc;                     // reuse weight region
        for (int i = tid; i < HD * 32; i += NTHR) {
            int u = i >> 5, j = i & 31;
            sw[i] = fc1w[(size_t)j * HD + u];
        }
        __syncthreads();
        if (tid < BSZ) {
            const uint4* hb = g_h1f[(TLEN - 1) & 1];
            float s[32];
            #pragma unroll
            for (int j = 0; j < 32; ++j) s[j] = 0.0f;
            for (int u = 0; u < HD; ++u) {
                uint4 q = __ldcg(&hb[FIDX(tid >> 4, u >> 4, (tid & 7) * 4 + ((u & 7) >> 1))]);
                uint32_t rg = ((const uint32_t*)&q)[((tid >> 3) & 1) + 2 * ((u >> 3) & 1)];
                float v = __bfloat162float(((const __nv_bfloat16*)&rg)[u & 1]);
                const float4* ww = (const float4*)(sw + u * 32);
                #pragma unroll
                for (int j4 = 0; j4 < 8; ++j4) {
                    float4 wv = ww[j4];
                    s[4 * j4 + 0] += v * wv.x;
                    s[4 * j4 + 1] += v * wv.y;
                    s[4 * j4 + 2] += v * wv.z;
                    s[4 * j4 + 3] += v * wv.w;
                }
            }
            float y = fc2b[0];
            #pragma unroll
            for (int j = 0; j < 32; ++j) y += fc2w[j] * (s[j] + fc1b[j]);
            out[tid] = y;
        }
        __syncthreads();
    }

    // ---------------- finalize: reset counters for graph replay ----------------
    __syncthreads();
    __threadfence();
    if (tid == 0) {
        if (atomicAdd(&g_finp[0], 1u) == NALL - 1) {
            g_cnt0p[0] = 0;
            g_cnt1p[0] = 0;
            __threadfence();
            atomicExch(&g_finp[0], 0u);
        }
    }
}

// =====================================================================
extern "C" void kernel_launch(void* const* d_in, const int* in_sizes, int n_in,
                              void* d_out, int out_size)
{
    (void)in_sizes; (void)n_in; (void)out_size;
    const float* x    = (const float*)d_in[0];
    const float* Wih0 = (const float*)d_in[1];
    const float* Whh0 = (const float*)d_in[2];
    const float* bih0 = (const float*)d_in[3];
    const float* bhh0 = (const float*)d_in[4];
    const float* Wih1 = (const float*)d_in[5];
    const float* Whh1 = (const float*)d_in[6];
    const float* bih1 = (const float*)d_in[7];
    const float* bhh1 = (const float*)d_in[8];
    const float* fc1w = (const float*)d_in[9];
    const float* fc1b = (const float*)d_in[10];
    const float* fc2w = (const float*)d_in[11];
    const float* fc2b = (const float*)d_in[12];
    float* out = (float*)d_out;

    const int sm_x = 64 * XW_ST * 4 + 256;
    cudaFuncSetAttribute(xform0, cudaFuncAttributeMaxDynamicSharedMemorySize, sm_x);
    cudaFuncSetAttribute(rec,    cudaFuncAttributeMaxDynamicSharedMemorySize, SMEM_REC);

    xform0<<<dim3(N0CTA, TLEN / 8), NTHR, sm_x>>>(x, Wih0, bih0, bhh0);
    rec<<<NALL, NTHR, SMEM_REC>>>(Whh0, Wih1, Whh1, bih1, bhh1,
                                  fc1w, fc1b, fc2w, fc2b, out);
}